// round 11
// baseline (speedup 1.0000x reference)
#include <cuda_runtime.h>
#include <cuda_bf16.h>
#include <math.h>
#include <stdint.h>

#define TT   2048
#define DD   1024
#define NH   16
#define HDIM 64
#define WIN  128
#define PSTR 132
#define IT   16
#define JTA  148
#define SIT  64     // scores i-tile
#define SPAN 192    // scores j-window (64 + 128)

// ---------------- scratch (static device globals; no allocation) ----------
__device__ float v_buf[TT * DD];
__device__ float norm_buf[NH * TT];
__device__ float denom_buf[NH * TT];
__device__ float suminv_buf[NH];
__device__ float p_buf[(size_t)NH * TT * PSTR];

__device__ __nv_bfloat16 xh_buf[TT * DD], xl_buf[TT * DD];
__device__ __nv_bfloat16 gh_buf[TT * DD], gl_buf[TT * DD];
__device__ __nv_bfloat16 oh_buf[TT * DD], ol_buf[TT * DD];
__device__ __nv_bfloat16 wgh_buf[DD * DD], wgl_buf[DD * DD];
__device__ __nv_bfloat16 wvh_buf[DD * DD], wvl_buf[DD * DD];
__device__ __nv_bfloat16 woh_buf[DD * DD], wol_buf[DD * DD];

// ---------------- PTX helpers ----------------------------------------------
__device__ __forceinline__ uint32_t s2u(const void* p) {
    uint32_t a;
    asm("{ .reg .u64 t; cvta.to.shared.u64 t, %1; cvt.u32.u64 %0, t; }"
        : "=r"(a) : "l"(p));
    return a;
}
#define CP_ASYNC16(dst, src) \
    asm volatile("cp.async.cg.shared.global [%0], [%1], 16;" :: "r"(dst), "l"(src))
#define CP_COMMIT()  asm volatile("cp.async.commit_group;" ::: "memory")
#define CP_WAIT1()   asm volatile("cp.async.wait_group 1;" ::: "memory")
#define CP_WAIT0()   asm volatile("cp.async.wait_group 0;" ::: "memory")

__device__ __forceinline__ void ldsm_x4(uint32_t& r0, uint32_t& r1,
                                        uint32_t& r2, uint32_t& r3, uint32_t a) {
    asm volatile("ldmatrix.sync.aligned.m8n8.x4.shared.b16 {%0,%1,%2,%3}, [%4];"
                 : "=r"(r0), "=r"(r1), "=r"(r2), "=r"(r3) : "r"(a));
}
__device__ __forceinline__ void mma16816(float* d, const uint32_t* a, const uint32_t* b) {
    asm volatile(
        "mma.sync.aligned.m16n8k16.row.col.f32.bf16.bf16.f32 "
        "{%0,%1,%2,%3}, {%4,%5,%6,%7}, {%8,%9}, {%0,%1,%2,%3};"
        : "+f"(d[0]), "+f"(d[1]), "+f"(d[2]), "+f"(d[3])
        : "r"(a[0]), "r"(a[1]), "r"(a[2]), "r"(a[3]), "r"(b[0]), "r"(b[1]));
}
__device__ __forceinline__ uint32_t sw64(uint32_t off) {
    return off ^ ((off >> 3) & 0x30u);
}
__device__ __forceinline__ uint32_t sw128(uint32_t off) {
    return off ^ ((off >> 3) & 0x70u);
}

// ---------------- fp32->bf16 hi/lo split ------------------------------------
__device__ __forceinline__ void split_store(const float* __restrict__ src,
                                            __nv_bfloat16* __restrict__ dh,
                                            __nv_bfloat16* __restrict__ dl, int i)
{
    float4 v = ((const float4*)src)[i];
    __nv_bfloat16 h0 = __float2bfloat16(v.x), h1 = __float2bfloat16(v.y),
                  h2 = __float2bfloat16(v.z), h3 = __float2bfloat16(v.w);
    __nv_bfloat16 l0 = __float2bfloat16(v.x - __bfloat162float(h0)),
                  l1 = __float2bfloat16(v.y - __bfloat162float(h1)),
                  l2 = __float2bfloat16(v.z - __bfloat162float(h2)),
                  l3 = __float2bfloat16(v.w - __bfloat162float(h3));
    __nv_bfloat162 hp0(h0, h1), hp1(h2, h3), lp0(l0, l1), lp1(l2, l3);
    uint2 uh, ul;
    uh.x = *(unsigned*)&hp0; uh.y = *(unsigned*)&hp1;
    ul.x = *(unsigned*)&lp0; ul.y = *(unsigned*)&lp1;
    ((uint2*)dh)[i] = uh;
    ((uint2*)dl)[i] = ul;
}

__global__ void __launch_bounds__(256)
k_conv_all(const float* __restrict__ x,  const float* __restrict__ Wg,
           const float* __restrict__ Wv, const float* __restrict__ Wo)
{
    const int b = blockIdx.x;
    if (b == 0 && threadIdx.x < NH) suminv_buf[threadIdx.x] = 0.f;
    const float* src; __nv_bfloat16 *dh, *dl; int base;
    if (b < 1024)      { src = x;  dh = xh_buf;  dl = xl_buf;  base = b; }
    else if (b < 1536) { src = Wg; dh = wgh_buf; dl = wgl_buf; base = b - 1024; }
    else if (b < 2048) { src = Wv; dh = wvh_buf; dl = wvl_buf; base = b - 1536; }
    else               { src = Wo; dh = woh_buf; dl = wol_buf; base = b - 2048; }
    const int i = base * 512 + threadIdx.x;
    split_store(src, dh, dl, i);
    split_store(src, dh, dl, i + 256);
}

// ---------------- HMMA bf16-split GEMM (3-stage, 3 CTA/SM) -------------------
#define KC32   32
#define NC     (DD / KC32)
#define ATSZ   8192
#define BTSZ   4096
#define STG    (2 * ATSZ + 2 * BTSZ)
#define NSTAGE 3
#define SMEM_G (NSTAGE * STG)       // 73728

__device__ __forceinline__ void load_stage(
    const uint4* __restrict__ Ah4, const uint4* __restrict__ Al4,
    const uint4* __restrict__ Bh4, const uint4* __restrict__ Bl4,
    uint32_t sb, int slot, int c, int m0, int n0, int tid)
{
    const uint32_t base = sb + slot * STG;
    const int q = tid & 3;
#pragma unroll
    for (int t = 0; t < 4; ++t) {
        const int row = (t * 64 + (tid >> 2)) & 127;
        const uint32_t dst = base + (t >> 1) * ATSZ + sw64((uint32_t)row * 64u + q * 16u);
        const uint4* src = ((t >> 1) ? Al4 : Ah4)
                         + (size_t)(m0 + row) * (DD / 8) + c * 4 + q;
        CP_ASYNC16(dst, src);
    }
#pragma unroll
    for (int t = 0; t < 2; ++t) {
        const int row = tid >> 2;
        const uint32_t dst = base + 2 * ATSZ + t * BTSZ
                           + sw64((uint32_t)row * 64u + q * 16u);
        const uint4* src = (t ? Bl4 : Bh4)
                         + (size_t)(n0 + row) * (DD / 8) + c * 4 + q;
        CP_ASYNC16(dst, src);
    }
}

__device__ __forceinline__ void gemm_core(
    const uint4* __restrict__ Ah4, const uint4* __restrict__ Al4,
    const uint4* __restrict__ Bh4, const uint4* __restrict__ Bl4,
    const float* __restrict__ bias, float* __restrict__ C, bool doNorm)
{
    extern __shared__ char smem[];
    __shared__ float ssrow[128];
    const uint32_t sb = s2u(smem);
    const int tid  = threadIdx.x;
    const int wid  = tid >> 5;
    const int lane = tid & 31;
    const int n0 = blockIdx.x * 64, m0 = blockIdx.y * 128;

    const int wm = wid >> 1;
    const int wn = wid & 1;

    const int r  = lane & 7;
    const int md = lane >> 3;
    const int rowA = wm * 32 + (md & 1) * 8 + r;
    const uint32_t bA = (md >> 1) * 16;
    const int rowB = wn * 32 + (md >> 1) * 8 + r;
    const uint32_t bB = (md & 1) * 16;

    if (doNorm && tid < 128) ssrow[tid] = 0.f;

    float acc[2][4][4];
#pragma unroll
    for (int f = 0; f < 2; ++f)
#pragma unroll
        for (int j = 0; j < 4; ++j)
#pragma unroll
            for (int e = 0; e < 4; ++e) acc[f][j][e] = 0.f;

    load_stage(Ah4, Al4, Bh4, Bl4, sb, 0, 0, m0, n0, tid); CP_COMMIT();
    load_stage(Ah4, Al4, Bh4, Bl4, sb, 1, 1, m0, n0, tid); CP_COMMIT();

#pragma unroll 1
    for (int c = 0; c < NC; ++c) {
        if (c < NC - 1) CP_WAIT1(); else CP_WAIT0();
        __syncthreads();

        const int slot = c % NSTAGE;
        const uint32_t base = sb + slot * STG;
        const uint32_t stAh = base;
        const uint32_t stAl = base + ATSZ;
        const uint32_t stBh = base + 2 * ATSZ;
        const uint32_t stBl = base + 2 * ATSZ + BTSZ;

#pragma unroll
        for (int ks = 0; ks < 2; ++ks) {
            const uint32_t kb = ks * 32;
            uint32_t ah[2][4], al[2][4];
#pragma unroll
            for (int f = 0; f < 2; ++f) {
                const uint32_t off = sw64((uint32_t)(rowA + f * 16) * 64u + kb + bA);
                ldsm_x4(ah[f][0], ah[f][1], ah[f][2], ah[f][3], stAh + off);
                ldsm_x4(al[f][0], al[f][1], al[f][2], al[f][3], stAl + off);
            }
            uint32_t bh[4][2], bl[4][2];
#pragma unroll
            for (int p = 0; p < 2; ++p) {
                const uint32_t off = sw64((uint32_t)(rowB + p * 16) * 64u + kb + bB);
                ldsm_x4(bh[2*p][0], bh[2*p][1], bh[2*p+1][0], bh[2*p+1][1], stBh + off);
                ldsm_x4(bl[2*p][0], bl[2*p][1], bl[2*p+1][0], bl[2*p+1][1], stBl + off);
            }
#pragma unroll
            for (int f = 0; f < 2; ++f)
#pragma unroll
                for (int j = 0; j < 4; ++j) {
                    mma16816(acc[f][j], ah[f], bh[j]);
                    mma16816(acc[f][j], ah[f], bl[j]);
                    mma16816(acc[f][j], al[f], bh[j]);
                }
        }
        if (c + 2 < NC) {
            load_stage(Ah4, Al4, Bh4, Bl4, sb, (c + 2) % NSTAGE, c + 2, m0, n0, tid);
            CP_COMMIT();
        }
    }

    // epilogue
#pragma unroll
    for (int f = 0; f < 2; ++f) {
        const int grow = m0 + wm * 32 + f * 16 + (lane >> 2);
        float ss0 = 0.f, ss1 = 0.f;
#pragma unroll
        for (int j = 0; j < 4; ++j) {
            const int col = n0 + wn * 32 + j * 8 + (lane & 3) * 2;
            const float2 bb = *(const float2*)(bias + col);
            float2 o0 = make_float2(acc[f][j][0] + bb.x, acc[f][j][1] + bb.y);
            float2 o1 = make_float2(acc[f][j][2] + bb.x, acc[f][j][3] + bb.y);
            if (doNorm) {
                const size_t p0 = ((size_t)grow * DD + col) >> 1;
                const size_t p1 = ((size_t)(grow + 8) * DD + col) >> 1;
                __nv_bfloat16 h00 = __float2bfloat16(o0.x), h01 = __float2bfloat16(o0.y);
                __nv_bfloat16 h10 = __float2bfloat16(o1.x), h11 = __float2bfloat16(o1.y);
                __nv_bfloat16 l00 = __float2bfloat16(o0.x - __bfloat162float(h00));
                __nv_bfloat16 l01 = __float2bfloat16(o0.y - __bfloat162float(h01));
                __nv_bfloat16 l10 = __float2bfloat16(o1.x - __bfloat162float(h10));
                __nv_bfloat16 l11 = __float2bfloat16(o1.y - __bfloat162float(h11));
                ((__nv_bfloat162*)gh_buf)[p0] = __nv_bfloat162(h00, h01);
                ((__nv_bfloat162*)gl_buf)[p0] = __nv_bfloat162(l00, l01);
                ((__nv_bfloat162*)gh_buf)[p1] = __nv_bfloat162(h10, h11);
                ((__nv_bfloat162*)gl_buf)[p1] = __nv_bfloat162(l10, l11);
                ss0 = fmaf(o0.x, o0.x, fmaf(o0.y, o0.y, ss0));
                ss1 = fmaf(o1.x, o1.x, fmaf(o1.y, o1.y, ss1));
            } else {
                float* c0 = C + (size_t)grow * DD;
                *(float2*)(c0 + col) = o0;
                *(float2*)(c0 + 8 * DD + col) = o1;
            }
        }
        if (doNorm) {
            ss0 += __shfl_xor_sync(0xffffffffu, ss0, 1);
            ss0 += __shfl_xor_sync(0xffffffffu, ss0, 2);
            ss1 += __shfl_xor_sync(0xffffffffu, ss1, 1);
            ss1 += __shfl_xor_sync(0xffffffffu, ss1, 2);
            if ((lane & 3) == 0) {
                const int l0 = wm * 32 + f * 16 + (lane >> 2);
                atomicAdd(&ssrow[l0], ss0);
                atomicAdd(&ssrow[l0 + 8], ss1);
            }
        }
    }
    if (doNorm) {
        __syncthreads();
        if (tid < 128) {
            const int h = n0 >> 6;
            norm_buf[h * TT + m0 + tid] = sqrtf(ssrow[tid]);
        }
    }
}

__global__ void __launch_bounds__(256, 3)
k_gemm_gv(const float* __restrict__ bg, const float* __restrict__ bv)
{
    if (blockIdx.z == 0)
        gemm_core((const uint4*)xh_buf, (const uint4*)xl_buf,
                  (const uint4*)wgh_buf, (const uint4*)wgl_buf, bg, nullptr, true);
    else
        gemm_core((const uint4*)xh_buf, (const uint4*)xl_buf,
                  (const uint4*)wvh_buf, (const uint4*)wvl_buf, bv, v_buf, false);
}

__global__ void __launch_bounds__(256, 3)
k_gemm_o(const float* __restrict__ bo, float* __restrict__ out)
{
    gemm_core((const uint4*)oh_buf, (const uint4*)ol_buf,
              (const uint4*)woh_buf, (const uint4*)wol_buf, bo, out, false);
}

// ---------------- MMA banded scores ------------------------------------------
#define WTSZ   (SPAN * 128)
#define SMEM_S (2 * WTSZ)

__global__ void __launch_bounds__(256)
k_scores_mma()
{
    extern __shared__ char smem[];
    __shared__ float nwin[SPAN];
    __shared__ float rowsum[SIT];
    __shared__ float sinv[SIT];

    const uint32_t sbH = s2u(smem);
    const uint32_t sbL = sbH + WTSZ;
    const int tid  = threadIdx.x;
    const int wid  = tid >> 5;
    const int lane = tid & 31;
    const int i0 = blockIdx.x * SIT;
    const int h  = blockIdx.y;

    const int jstart0 = (i0 > WIN) ? (i0 - WIN) : 0;
    const int qbase   = i0 - jstart0;

    const uint4* gh4 = (const uint4*)gh_buf;
    const uint4* gl4 = (const uint4*)gl_buf;
#pragma unroll
    for (int t = 0; t < 6; ++t) {
        const int idx = t * 256 + tid;
        const int row = idx >> 3;
        const int q   = idx & 7;
        const uint32_t d = sw128((uint32_t)row * 128u + q * 16u);
        const size_t g = (size_t)(jstart0 + row) * (DD / 8) + h * 8 + q;
        CP_ASYNC16(sbH + d, gh4 + g);
        CP_ASYNC16(sbL + d, gl4 + g);
    }
    CP_COMMIT();
    if (tid < SPAN) nwin[tid] = norm_buf[h * TT + jstart0 + tid];
    if (tid < SIT) rowsum[tid] = 0.f;
    CP_WAIT0();
    __syncthreads();

    const int wm = wid >> 1;
    const int wn = wid & 1;

    const int r  = lane & 7;
    const int md = lane >> 3;
    const int arow  = qbase + wm * 16 + (md & 1) * 8 + r;
    const uint32_t abyte = (md >> 1) * 16;
    const int brow0 = wn * 96 + (md >> 1) * 8 + r;
    const uint32_t bbyte = (md & 1) * 16;

    float acc[12][4];
#pragma unroll
    for (int nt = 0; nt < 12; ++nt)
#pragma unroll
        for (int e = 0; e < 4; ++e) acc[nt][e] = 0.f;

#pragma unroll
    for (int ks = 0; ks < 4; ++ks) {
        const uint32_t kb = ks * 32;
        uint32_t ah[4], al[4];
        const uint32_t aoff = sw128((uint32_t)arow * 128u + kb + abyte);
        ldsm_x4(ah[0], ah[1], ah[2], ah[3], sbH + aoff);
        ldsm_x4(al[0], al[1], al[2], al[3], sbL + aoff);
#pragma unroll
        for (int bt = 0; bt < 6; ++bt) {
            uint32_t bh[2][2], bl[2][2];
            const uint32_t boff = sw128((uint32_t)(brow0 + bt * 16) * 128u + kb + bbyte);
            ldsm_x4(bh[0][0], bh[0][1], bh[1][0], bh[1][1], sbH + boff);
            ldsm_x4(bl[0][0], bl[0][1], bl[1][0], bl[1][1], sbL + boff);
#pragma unroll
            for (int p = 0; p < 2; ++p) {
                mma16816(acc[2*bt + p], ah, bh[p]);
                mma16816(acc[2*bt + p], ah, bl[p]);
                mma16816(acc[2*bt + p], al, bh[p]);
            }
        }
    }

    const int quad = lane >> 2;
    const int cp2  = (lane & 3) * 2;
    const int gi0 = i0 + wm * 16 + quad;
    const int gi1 = gi0 + 8;
    const float ni0 = nwin[qbase + wm * 16 + quad];
    const float ni1 = nwin[qbase + wm * 16 + quad + 8];
    const int off0 = (gi0 > WIN) ? (gi0 - WIN) : 0;
    const int off1 = (gi1 > WIN) ? (gi1 - WIN) : 0;
    float* pr0 = p_buf + (size_t)(h * TT + gi0) * PSTR;
    float* pr1 = p_buf + (size_t)(h * TT + gi1) * PSTR;
    float ps0 = 0.f, ps1 = 0.f;

#pragma unroll
    for (int nt = 0; nt < 12; ++nt) {
        const int jl = wn * 96 + nt * 8 + cp2;
        const int jg = jstart0 + jl;
        const float nj0 = nwin[jl];
        const float nj1 = nwin[jl + 1];
#pragma unroll
        for (int e = 0; e < 4; ++e) {
            const int  jj = jg + (e & 1);
            const float nj = (e & 1) ? nj1 : nj0;
            const int  gi  = (e >> 1) ? gi1 : gi0;
            const float ni = (e >> 1) ? ni1 : ni0;
            const int  off = (e >> 1) ? off1 : off0;
            if (jj <= gi && jj >= off) {
                float c = acc[nt][e] / (ni * nj + 1e-8f);
                if (c != c) c = 0.f;
                float p = (c + 1.f) * 0.5f;
                ((e >> 1) ? pr1 : pr0)[jj - off] = p;
                if (e >> 1) ps1 += p; else ps0 += p;
            }
        }
    }

    ps0 += __shfl_xor_sync(0xffffffffu, ps0, 1);
    ps0 += __shfl_xor_sync(0xffffffffu, ps0, 2);
    ps1 += __shfl_xor_sync(0xffffffffu, ps1, 1);
    ps1 += __shfl_xor_sync(0xffffffffu, ps1, 2);
    if ((lane & 3) == 0) {
        atomicAdd(&rowsum[wm * 16 + quad], ps0);
        atomicAdd(&rowsum[wm * 16 + quad + 8], ps1);
    }
    __syncthreads();

    if (tid < SIT) {
        const int i   = i0 + tid;
        const int cnt = i - ((i > WIN) ? (i - WIN) : 0) + 1;
        float gm = (rowsum[tid] + 0.5f * (float)(TT - cnt)) * (1.f / (float)TT);
        float dn = gm + 0.5f;
        denom_buf[h * TT + i] = dn;
        sinv[tid] = 1.f / dn;
    }
    __syncthreads();
    if (tid < 32) {
        float s = sinv[tid] + sinv[tid + 32];
#pragma unroll
        for (int o = 16; o > 0; o >>= 1) s += __shfl_xor_sync(0xffffffffu, s, o);
        if (tid == 0) atomicAdd(&suminv_buf[h], s);
    }
}

// ---------------- softmax + attn@v (16 rows / block), no red[] --------------
#define SATT_STRIDE 20
#define ATTN_SMEM   (JTA * HDIM * 4 + JTA * SATT_STRIDE * 4 + 64)

__global__ void __launch_bounds__(256)
k_attnv()
{
    extern __shared__ char dynsm[];
    float (*vw)[HDIM]       = (float(*)[HDIM])dynsm;                 // [JTA][64]
    float (*sattn)[SATT_STRIDE] =
        (float(*)[SATT_STRIDE])(dynsm + JTA * HDIM * 4);             // [JTA][20]
    float* invs = (float*)(dynsm + JTA * HDIM * 4 + JTA * SATT_STRIDE * 4); // [16]

    const int i0  = blockIdx.x * IT;
    const int h   = blockIdx.y;
    const int tid = threadIdx.x;
    const int wid = tid >> 5;
    const int lane = tid & 31;

    const int jstart0 = (i0 > WIN) ? (i0 - WIN) : 0;
    const int span    = (i0 + IT - 1) - jstart0 + 1;

    const float4* v4 = (const float4*)v_buf;
    for (int idx = tid; idx < span * 16; idx += 256) {
        int jj = idx >> 4;
        int q  = idx & 15;
        ((float4*)&vw[jj][0])[q] = v4[(size_t)(jstart0 + jj) * (DD / 4) + h * (HDIM / 4) + q];
    }
    __syncthreads();

    // phase A: warp wid handles rows wid and wid+8
#pragma unroll
    for (int rr = 0; rr < 2; ++rr) {
        const int w = wid + rr * 8;
        const int i = i0 + w;
        const size_t row = (size_t)h * TT + i;
        const float fit  = 1.f / (denom_buf[row] * suminv_buf[h]);
        const int off = ((i > WIN) ? (i - WIN) : 0) - jstart0;
        const int wi  = i - jstart0;

        float m = -1e30f;
        for (int q = lane; q < JTA; q += 32) {
            bool in = (q >= off) && (q <= wi);
            float s = in ? fit * p_buf[row * PSTR + (q - off)] : -1e30f;
            sattn[q][w] = s;
            m = fmaxf(m, s);
        }
#pragma unroll
        for (int o = 16; o > 0; o >>= 1) m = fmaxf(m, __shfl_xor_sync(0xffffffffu, m, o));

        float ss = 0.f;
        for (int q = lane; q < JTA; q += 32) {
            float e = __expf(sattn[q][w] - m);
            sattn[q][w] = e;
            ss += e;
        }
#pragma unroll
        for (int o = 16; o > 0; o >>= 1) ss += __shfl_xor_sync(0xffffffffu, ss, o);
        if (lane == 0) invs[w] = 1.f / ss;
    }
    __syncthreads();

    // phase B: thread = (d, row-group); each runs full jj range for 4 rows
    {
        const int d   = tid & 63;
        const int grp = tid >> 6;              // 0..3 -> rows grp*4 .. grp*4+3
        float a0 = 0.f, a1 = 0.f, a2 = 0.f, a3 = 0.f;
        for (int jj = 0; jj < span; ++jj) {
            const float vv = vw[jj][d];
            const float4 s = *(const float4*)&sattn[jj][grp * 4];
            a0 = fmaf(s.x, vv, a0);
            a1 = fmaf(s.y, vv, a1);
            a2 = fmaf(s.z, vv, a2);
            a3 = fmaf(s.w, vv, a3);
        }
        const float r0 = a0 * invs[grp * 4 + 0];
        const float r1 = a1 * invs[grp * 4 + 1];
        const float r2 = a2 * invs[grp * 4 + 2];
        const float r3 = a3 * invs[grp * 4 + 3];
        const size_t base = (size_t)(i0 + grp * 4) * DD + h * HDIM + d;
#pragma unroll
        for (int rI = 0; rI < 4; ++rI) {
            const float val = (rI == 0) ? r0 : (rI == 1) ? r1 : (rI == 2) ? r2 : r3;
            const size_t idx = base + (size_t)rI * DD;
            __nv_bfloat16 hv = __float2bfloat16(val);
            __nv_bfloat16 lv = __float2bfloat16(val - __bfloat162float(hv));
            oh_buf[idx] = hv;
            ol_buf[idx] = lv;
        }
    }
}

// ---------------- launch ---------------------------------------------------
extern "C" void kernel_launch(void* const* d_in, const int* in_sizes, int n_in,
                              void* d_out, int out_size)
{
    const float* x  = (const float*)d_in[0];
    const float* Wg = (const float*)d_in[1];
    const float* bg = (const float*)d_in[2];
    const float* Wv = (const float*)d_in[3];
    const float* bv = (const float*)d_in[4];
    const float* Wo = (const float*)d_in[5];
    const float* bo = (const float*)d_in[6];
    float* out = (float*)d_out;

    cudaFuncSetAttribute(k_gemm_gv,   cudaFuncAttributeMaxDynamicSharedMemorySize, SMEM_G);
    cudaFuncSetAttribute(k_gemm_o,    cudaFuncAttributeMaxDynamicSharedMemorySize, SMEM_G);
    cudaFuncSetAttribute(k_scores_mma,cudaFuncAttributeMaxDynamicSharedMemorySize, SMEM_S);
    cudaFuncSetAttribute(k_attnv,     cudaFuncAttributeMaxDynamicSharedMemorySize, ATTN_SMEM);

    k_conv_all<<<2560, 256>>>(x, Wg, Wv, Wo);                 // #1

    dim3 gemm_gv(DD / 64, TT / 128, 2);
    k_gemm_gv<<<gemm_gv, 256, SMEM_G>>>(bg, bv);              // #2

    dim3 sc_grid(TT / SIT, NH);
    k_scores_mma<<<sc_grid, 256, SMEM_S>>>();                 // #3

    dim3 av_grid(TT / IT, NH);
    k_attnv<<<av_grid, 256, ATTN_SMEM>>>();                   // #4 (ncu slot)

    dim3 gemm_o(DD / 64, TT / 128, 1);
    k_gemm_o<<<gemm_o, 256, SMEM_G>>>(bo, out);               // #5
}

// round 12
// speedup vs baseline: 1.0526x; 1.0526x over previous
#include <cuda_runtime.h>
#include <cuda_bf16.h>
#include <math.h>
#include <stdint.h>

#define TT   2048
#define DD   1024
#define NH   16
#define HDIM 64
#define WIN  128
#define PSTR 132
#define IT   16
#define JTA  148
#define SIT  64     // scores i-tile
#define SPAN 192    // scores j-window (64 + 128)

// ---------------- scratch (static device globals; no allocation) ----------
__device__ float v_buf[TT * DD];
__device__ float norm_buf[NH * TT];
__device__ float denom_buf[NH * TT];
__device__ float suminv_buf[NH];
__device__ float p_buf[(size_t)NH * TT * PSTR];

__device__ __nv_bfloat16 xh_buf[TT * DD], xl_buf[TT * DD];
__device__ __nv_bfloat16 gh_buf[TT * DD], gl_buf[TT * DD];
__device__ __nv_bfloat16 oh_buf[TT * DD], ol_buf[TT * DD];
__device__ __nv_bfloat16 wgh_buf[DD * DD], wgl_buf[DD * DD];
__device__ __nv_bfloat16 wvh_buf[DD * DD], wvl_buf[DD * DD];
__device__ __nv_bfloat16 woh_buf[DD * DD], wol_buf[DD * DD];

// ---------------- PTX helpers ----------------------------------------------
__device__ __forceinline__ uint32_t s2u(const void* p) {
    uint32_t a;
    asm("{ .reg .u64 t; cvta.to.shared.u64 t, %1; cvt.u32.u64 %0, t; }"
        : "=r"(a) : "l"(p));
    return a;
}
#define CP_ASYNC16(dst, src) \
    asm volatile("cp.async.cg.shared.global [%0], [%1], 16;" :: "r"(dst), "l"(src))
#define CP_COMMIT()  asm volatile("cp.async.commit_group;" ::: "memory")
#define CP_WAIT2()   asm volatile("cp.async.wait_group 2;" ::: "memory")
#define CP_WAIT1()   asm volatile("cp.async.wait_group 1;" ::: "memory")
#define CP_WAIT0()   asm volatile("cp.async.wait_group 0;" ::: "memory")

__device__ __forceinline__ void ldsm_x4(uint32_t& r0, uint32_t& r1,
                                        uint32_t& r2, uint32_t& r3, uint32_t a) {
    asm volatile("ldmatrix.sync.aligned.m8n8.x4.shared.b16 {%0,%1,%2,%3}, [%4];"
                 : "=r"(r0), "=r"(r1), "=r"(r2), "=r"(r3) : "r"(a));
}
__device__ __forceinline__ void mma16816(float* d, const uint32_t* a, const uint32_t* b) {
    asm volatile(
        "mma.sync.aligned.m16n8k16.row.col.f32.bf16.bf16.f32 "
        "{%0,%1,%2,%3}, {%4,%5,%6,%7}, {%8,%9}, {%0,%1,%2,%3};"
        : "+f"(d[0]), "+f"(d[1]), "+f"(d[2]), "+f"(d[3])
        : "r"(a[0]), "r"(a[1]), "r"(a[2]), "r"(a[3]), "r"(b[0]), "r"(b[1]));
}
__device__ __forceinline__ uint32_t sw64(uint32_t off) {
    return off ^ ((off >> 3) & 0x30u);
}
__device__ __forceinline__ uint32_t sw128(uint32_t off) {
    return off ^ ((off >> 3) & 0x70u);
}

// ---------------- fp32->bf16 hi/lo split ------------------------------------
__device__ __forceinline__ void split_store(const float* __restrict__ src,
                                            __nv_bfloat16* __restrict__ dh,
                                            __nv_bfloat16* __restrict__ dl, int i)
{
    float4 v = ((const float4*)src)[i];
    __nv_bfloat16 h0 = __float2bfloat16(v.x), h1 = __float2bfloat16(v.y),
                  h2 = __float2bfloat16(v.z), h3 = __float2bfloat16(v.w);
    __nv_bfloat16 l0 = __float2bfloat16(v.x - __bfloat162float(h0)),
                  l1 = __float2bfloat16(v.y - __bfloat162float(h1)),
                  l2 = __float2bfloat16(v.z - __bfloat162float(h2)),
                  l3 = __float2bfloat16(v.w - __bfloat162float(h3));
    __nv_bfloat162 hp0(h0, h1), hp1(h2, h3), lp0(l0, l1), lp1(l2, l3);
    uint2 uh, ul;
    uh.x = *(unsigned*)&hp0; uh.y = *(unsigned*)&hp1;
    ul.x = *(unsigned*)&lp0; ul.y = *(unsigned*)&lp1;
    ((uint2*)dh)[i] = uh;
    ((uint2*)dl)[i] = ul;
}

__global__ void __launch_bounds__(256)
k_conv_all(const float* __restrict__ x,  const float* __restrict__ Wg,
           const float* __restrict__ Wv, const float* __restrict__ Wo)
{
    const int b = blockIdx.x;
    if (b == 0 && threadIdx.x < NH) suminv_buf[threadIdx.x] = 0.f;
    const float* src; __nv_bfloat16 *dh, *dl; int base;
    if (b < 1024)      { src = x;  dh = xh_buf;  dl = xl_buf;  base = b; }
    else if (b < 1536) { src = Wg; dh = wgh_buf; dl = wgl_buf; base = b - 1024; }
    else if (b < 2048) { src = Wv; dh = wvh_buf; dl = wvl_buf; base = b - 1536; }
    else               { src = Wo; dh = woh_buf; dl = wol_buf; base = b - 2048; }
    const int i = base * 512 + threadIdx.x;
    split_store(src, dh, dl, i);
    split_store(src, dh, dl, i + 256);
}

// ---------------- HMMA bf16-split GEMM (4-stage, 2 CTA/SM — round-10 cfg) ---
#define KC32   32
#define NC     (DD / KC32)
#define ATSZ   8192
#define BTSZ   4096
#define STG    (2 * ATSZ + 2 * BTSZ)
#define NSTAGE 4
#define SMEM_G (NSTAGE * STG)       // 98304

__device__ __forceinline__ void load_stage(
    const uint4* __restrict__ Ah4, const uint4* __restrict__ Al4,
    const uint4* __restrict__ Bh4, const uint4* __restrict__ Bl4,
    uint32_t sb, int slot, int c, int m0, int n0, int tid)
{
    const uint32_t base = sb + slot * STG;
    const int q = tid & 3;
#pragma unroll
    for (int t = 0; t < 4; ++t) {
        const int row = (t * 64 + (tid >> 2)) & 127;
        const uint32_t dst = base + (t >> 1) * ATSZ + sw64((uint32_t)row * 64u + q * 16u);
        const uint4* src = ((t >> 1) ? Al4 : Ah4)
                         + (size_t)(m0 + row) * (DD / 8) + c * 4 + q;
        CP_ASYNC16(dst, src);
    }
#pragma unroll
    for (int t = 0; t < 2; ++t) {
        const int row = tid >> 2;
        const uint32_t dst = base + 2 * ATSZ + t * BTSZ
                           + sw64((uint32_t)row * 64u + q * 16u);
        const uint4* src = (t ? Bl4 : Bh4)
                         + (size_t)(n0 + row) * (DD / 8) + c * 4 + q;
        CP_ASYNC16(dst, src);
    }
}

__device__ __forceinline__ void gemm_core(
    const uint4* __restrict__ Ah4, const uint4* __restrict__ Al4,
    const uint4* __restrict__ Bh4, const uint4* __restrict__ Bl4,
    const float* __restrict__ bias, float* __restrict__ C, bool doNorm)
{
    extern __shared__ char smem[];
    __shared__ float ssrow[128];
    const uint32_t sb = s2u(smem);
    const int tid  = threadIdx.x;
    const int wid  = tid >> 5;
    const int lane = tid & 31;
    const int n0 = blockIdx.x * 64, m0 = blockIdx.y * 128;

    const int wm = wid >> 1;
    const int wn = wid & 1;

    const int r  = lane & 7;
    const int md = lane >> 3;
    const int rowA = wm * 32 + (md & 1) * 8 + r;
    const uint32_t bA = (md >> 1) * 16;
    const int rowB = wn * 32 + (md >> 1) * 8 + r;
    const uint32_t bB = (md & 1) * 16;

    if (doNorm && tid < 128) ssrow[tid] = 0.f;

    float acc[2][4][4];
#pragma unroll
    for (int f = 0; f < 2; ++f)
#pragma unroll
        for (int j = 0; j < 4; ++j)
#pragma unroll
            for (int e = 0; e < 4; ++e) acc[f][j][e] = 0.f;

    load_stage(Ah4, Al4, Bh4, Bl4, sb, 0, 0, m0, n0, tid); CP_COMMIT();
    load_stage(Ah4, Al4, Bh4, Bl4, sb, 1, 1, m0, n0, tid); CP_COMMIT();
    load_stage(Ah4, Al4, Bh4, Bl4, sb, 2, 2, m0, n0, tid); CP_COMMIT();

#pragma unroll 1
    for (int c = 0; c < NC; ++c) {
        const int rem = NC - 1 - c;
        if (rem >= 2) CP_WAIT2(); else if (rem == 1) CP_WAIT1(); else CP_WAIT0();
        __syncthreads();

        const uint32_t base = sb + (c & 3) * STG;
        const uint32_t stAh = base;
        const uint32_t stAl = base + ATSZ;
        const uint32_t stBh = base + 2 * ATSZ;
        const uint32_t stBl = base + 2 * ATSZ + BTSZ;

#pragma unroll
        for (int ks = 0; ks < 2; ++ks) {
            const uint32_t kb = ks * 32;
            uint32_t ah[2][4], al[2][4];
#pragma unroll
            for (int f = 0; f < 2; ++f) {
                const uint32_t off = sw64((uint32_t)(rowA + f * 16) * 64u + kb + bA);
                ldsm_x4(ah[f][0], ah[f][1], ah[f][2], ah[f][3], stAh + off);
                ldsm_x4(al[f][0], al[f][1], al[f][2], al[f][3], stAl + off);
            }
            uint32_t bh[4][2], bl[4][2];
#pragma unroll
            for (int p = 0; p < 2; ++p) {
                const uint32_t off = sw64((uint32_t)(rowB + p * 16) * 64u + kb + bB);
                ldsm_x4(bh[2*p][0], bh[2*p][1], bh[2*p+1][0], bh[2*p+1][1], stBh + off);
                ldsm_x4(bl[2*p][0], bl[2*p][1], bl[2*p+1][0], bl[2*p+1][1], stBl + off);
            }
#pragma unroll
            for (int f = 0; f < 2; ++f)
#pragma unroll
                for (int j = 0; j < 4; ++j) {
                    mma16816(acc[f][j], ah[f], bh[j]);
                    mma16816(acc[f][j], ah[f], bl[j]);
                    mma16816(acc[f][j], al[f], bh[j]);
                }
        }
        if (c + 3 < NC) {
            load_stage(Ah4, Al4, Bh4, Bl4, sb, (c + 3) & 3, c + 3, m0, n0, tid);
            CP_COMMIT();
        }
    }

    // epilogue
#pragma unroll
    for (int f = 0; f < 2; ++f) {
        const int grow = m0 + wm * 32 + f * 16 + (lane >> 2);
        float ss0 = 0.f, ss1 = 0.f;
#pragma unroll
        for (int j = 0; j < 4; ++j) {
            const int col = n0 + wn * 32 + j * 8 + (lane & 3) * 2;
            const float2 bb = *(const float2*)(bias + col);
            float2 o0 = make_float2(acc[f][j][0] + bb.x, acc[f][j][1] + bb.y);
            float2 o1 = make_float2(acc[f][j][2] + bb.x, acc[f][j][3] + bb.y);
            if (doNorm) {
                const size_t p0 = ((size_t)grow * DD + col) >> 1;
                const size_t p1 = ((size_t)(grow + 8) * DD + col) >> 1;
                __nv_bfloat16 h00 = __float2bfloat16(o0.x), h01 = __float2bfloat16(o0.y);
                __nv_bfloat16 h10 = __float2bfloat16(o1.x), h11 = __float2bfloat16(o1.y);
                __nv_bfloat16 l00 = __float2bfloat16(o0.x - __bfloat162float(h00));
                __nv_bfloat16 l01 = __float2bfloat16(o0.y - __bfloat162float(h01));
                __nv_bfloat16 l10 = __float2bfloat16(o1.x - __bfloat162float(h10));
                __nv_bfloat16 l11 = __float2bfloat16(o1.y - __bfloat162float(h11));
                ((__nv_bfloat162*)gh_buf)[p0] = __nv_bfloat162(h00, h01);
                ((__nv_bfloat162*)gl_buf)[p0] = __nv_bfloat162(l00, l01);
                ((__nv_bfloat162*)gh_buf)[p1] = __nv_bfloat162(h10, h11);
                ((__nv_bfloat162*)gl_buf)[p1] = __nv_bfloat162(l10, l11);
                ss0 = fmaf(o0.x, o0.x, fmaf(o0.y, o0.y, ss0));
                ss1 = fmaf(o1.x, o1.x, fmaf(o1.y, o1.y, ss1));
            } else {
                float* c0 = C + (size_t)grow * DD;
                *(float2*)(c0 + col) = o0;
                *(float2*)(c0 + 8 * DD + col) = o1;
            }
        }
        if (doNorm) {
            ss0 += __shfl_xor_sync(0xffffffffu, ss0, 1);
            ss0 += __shfl_xor_sync(0xffffffffu, ss0, 2);
            ss1 += __shfl_xor_sync(0xffffffffu, ss1, 1);
            ss1 += __shfl_xor_sync(0xffffffffu, ss1, 2);
            if ((lane & 3) == 0) {
                const int l0 = wm * 32 + f * 16 + (lane >> 2);
                atomicAdd(&ssrow[l0], ss0);
                atomicAdd(&ssrow[l0 + 8], ss1);
            }
        }
    }
    if (doNorm) {
        __syncthreads();
        if (tid < 128) {
            const int h = n0 >> 6;
            norm_buf[h * TT + m0 + tid] = sqrtf(ssrow[tid]);
        }
    }
}

__global__ void __launch_bounds__(256, 2)
k_gemm_gv(const float* __restrict__ bg, const float* __restrict__ bv)
{
    if (blockIdx.z == 0)
        gemm_core((const uint4*)xh_buf, (const uint4*)xl_buf,
                  (const uint4*)wgh_buf, (const uint4*)wgl_buf, bg, nullptr, true);
    else
        gemm_core((const uint4*)xh_buf, (const uint4*)xl_buf,
                  (const uint4*)wvh_buf, (const uint4*)wvl_buf, bv, v_buf, false);
}

__global__ void __launch_bounds__(256, 2)
k_gemm_o(const float* __restrict__ bo, float* __restrict__ out)
{
    gemm_core((const uint4*)oh_buf, (const uint4*)ol_buf,
              (const uint4*)woh_buf, (const uint4*)wol_buf, bo, out, false);
}

// ---------------- MMA banded scores ------------------------------------------
#define WTSZ   (SPAN * 128)
#define SMEM_S (2 * WTSZ)

__global__ void __launch_bounds__(256)
k_scores_mma()
{
    extern __shared__ char smem[];
    __shared__ float nwin[SPAN];
    __shared__ float rowsum[SIT];
    __shared__ float sinv[SIT];

    const uint32_t sbH = s2u(smem);
    const uint32_t sbL = sbH + WTSZ;
    const int tid  = threadIdx.x;
    const int wid  = tid >> 5;
    const int lane = tid & 31;
    const int i0 = blockIdx.x * SIT;
    const int h  = blockIdx.y;

    const int jstart0 = (i0 > WIN) ? (i0 - WIN) : 0;
    const int qbase   = i0 - jstart0;

    const uint4* gh4 = (const uint4*)gh_buf;
    const uint4* gl4 = (const uint4*)gl_buf;
#pragma unroll
    for (int t = 0; t < 6; ++t) {
        const int idx = t * 256 + tid;
        const int row = idx >> 3;
        const int q   = idx & 7;
        const uint32_t d = sw128((uint32_t)row * 128u + q * 16u);
        const size_t g = (size_t)(jstart0 + row) * (DD / 8) + h * 8 + q;
        CP_ASYNC16(sbH + d, gh4 + g);
        CP_ASYNC16(sbL + d, gl4 + g);
    }
    CP_COMMIT();
    if (tid < SPAN) nwin[tid] = norm_buf[h * TT + jstart0 + tid];
    if (tid < SIT) rowsum[tid] = 0.f;
    CP_WAIT0();
    __syncthreads();

    const int wm = wid >> 1;
    const int wn = wid & 1;

    const int r  = lane & 7;
    const int md = lane >> 3;
    const int arow  = qbase + wm * 16 + (md & 1) * 8 + r;
    const uint32_t abyte = (md >> 1) * 16;
    const int brow0 = wn * 96 + (md >> 1) * 8 + r;
    const uint32_t bbyte = (md & 1) * 16;

    float acc[12][4];
#pragma unroll
    for (int nt = 0; nt < 12; ++nt)
#pragma unroll
        for (int e = 0; e < 4; ++e) acc[nt][e] = 0.f;

#pragma unroll
    for (int ks = 0; ks < 4; ++ks) {
        const uint32_t kb = ks * 32;
        uint32_t ah[4], al[4];
        const uint32_t aoff = sw128((uint32_t)arow * 128u + kb + abyte);
        ldsm_x4(ah[0], ah[1], ah[2], ah[3], sbH + aoff);
        ldsm_x4(al[0], al[1], al[2], al[3], sbL + aoff);
#pragma unroll
        for (int bt = 0; bt < 6; ++bt) {
            uint32_t bh[2][2], bl[2][2];
            const uint32_t boff = sw128((uint32_t)(brow0 + bt * 16) * 128u + kb + bbyte);
            ldsm_x4(bh[0][0], bh[0][1], bh[1][0], bh[1][1], sbH + boff);
            ldsm_x4(bl[0][0], bl[0][1], bl[1][0], bl[1][1], sbL + boff);
#pragma unroll
            for (int p = 0; p < 2; ++p) {
                mma16816(acc[2*bt + p], ah, bh[p]);
                mma16816(acc[2*bt + p], ah, bl[p]);
                mma16816(acc[2*bt + p], al, bh[p]);
            }
        }
    }

    const int quad = lane >> 2;
    const int cp2  = (lane & 3) * 2;
    const int gi0 = i0 + wm * 16 + quad;
    const int gi1 = gi0 + 8;
    const float ni0 = nwin[qbase + wm * 16 + quad];
    const float ni1 = nwin[qbase + wm * 16 + quad + 8];
    const int off0 = (gi0 > WIN) ? (gi0 - WIN) : 0;
    const int off1 = (gi1 > WIN) ? (gi1 - WIN) : 0;
    float* pr0 = p_buf + (size_t)(h * TT + gi0) * PSTR;
    float* pr1 = p_buf + (size_t)(h * TT + gi1) * PSTR;
    float ps0 = 0.f, ps1 = 0.f;

#pragma unroll
    for (int nt = 0; nt < 12; ++nt) {
        const int jl = wn * 96 + nt * 8 + cp2;
        const int jg = jstart0 + jl;
        const float nj0 = nwin[jl];
        const float nj1 = nwin[jl + 1];
#pragma unroll
        for (int e = 0; e < 4; ++e) {
            const int  jj = jg + (e & 1);
            const float nj = (e & 1) ? nj1 : nj0;
            const int  gi  = (e >> 1) ? gi1 : gi0;
            const float ni = (e >> 1) ? ni1 : ni0;
            const int  off = (e >> 1) ? off1 : off0;
            if (jj <= gi && jj >= off) {
                float c = acc[nt][e] / (ni * nj + 1e-8f);
                if (c != c) c = 0.f;
                float p = (c + 1.f) * 0.5f;
                ((e >> 1) ? pr1 : pr0)[jj - off] = p;
                if (e >> 1) ps1 += p; else ps0 += p;
            }
        }
    }

    ps0 += __shfl_xor_sync(0xffffffffu, ps0, 1);
    ps0 += __shfl_xor_sync(0xffffffffu, ps0, 2);
    ps1 += __shfl_xor_sync(0xffffffffu, ps1, 1);
    ps1 += __shfl_xor_sync(0xffffffffu, ps1, 2);
    if ((lane & 3) == 0) {
        atomicAdd(&rowsum[wm * 16 + quad], ps0);
        atomicAdd(&rowsum[wm * 16 + quad + 8], ps1);
    }
    __syncthreads();

    if (tid < SIT) {
        const int i   = i0 + tid;
        const int cnt = i - ((i > WIN) ? (i - WIN) : 0) + 1;
        float gm = (rowsum[tid] + 0.5f * (float)(TT - cnt)) * (1.f / (float)TT);
        float dn = gm + 0.5f;
        denom_buf[h * TT + i] = dn;
        sinv[tid] = 1.f / dn;
    }
    __syncthreads();
    if (tid < 32) {
        float s = sinv[tid] + sinv[tid + 32];
#pragma unroll
        for (int o = 16; o > 0; o >>= 1) s += __shfl_xor_sync(0xffffffffu, s, o);
        if (tid == 0) atomicAdd(&suminv_buf[h], s);
    }
}

// ---------------- softmax + attn@v (16 rows / block), no red[] --------------
#define SATT_STRIDE 20
#define ATTN_SMEM   (JTA * HDIM * 4 + JTA * SATT_STRIDE * 4 + 64)

__global__ void __launch_bounds__(256)
k_attnv()
{
    extern __shared__ char dynsm[];
    float (*vw)[HDIM]       = (float(*)[HDIM])dynsm;                 // [JTA][64]
    float (*sattn)[SATT_STRIDE] =
        (float(*)[SATT_STRIDE])(dynsm + JTA * HDIM * 4);             // [JTA][20]
    float* invs = (float*)(dynsm + JTA * HDIM * 4 + JTA * SATT_STRIDE * 4); // [16]

    const int i0  = blockIdx.x * IT;
    const int h   = blockIdx.y;
    const int tid = threadIdx.x;
    const int wid = tid >> 5;
    const int lane = tid & 31;

    const int jstart0 = (i0 > WIN) ? (i0 - WIN) : 0;
    const int span    = (i0 + IT - 1) - jstart0 + 1;

    const float4* v4 = (const float4*)v_buf;
    for (int idx = tid; idx < span * 16; idx += 256) {
        int jj = idx >> 4;
        int q  = idx & 15;
        ((float4*)&vw[jj][0])[q] = v4[(size_t)(jstart0 + jj) * (DD / 4) + h * (HDIM / 4) + q];
    }
    __syncthreads();

#pragma unroll
    for (int rr = 0; rr < 2; ++rr) {
        const int w = wid + rr * 8;
        const int i = i0 + w;
        const size_t row = (size_t)h * TT + i;
        const float fit  = 1.f / (denom_buf[row] * suminv_buf[h]);
        const int off = ((i > WIN) ? (i - WIN) : 0) - jstart0;
        const int wi  = i - jstart0;

        float m = -1e30f;
        for (int q = lane; q < JTA; q += 32) {
            bool in = (q >= off) && (q <= wi);
            float s = in ? fit * p_buf[row * PSTR + (q - off)] : -1e30f;
            sattn[q][w] = s;
            m = fmaxf(m, s);
        }
#pragma unroll
        for (int o = 16; o > 0; o >>= 1) m = fmaxf(m, __shfl_xor_sync(0xffffffffu, m, o));

        float ss = 0.f;
        for (int q = lane; q < JTA; q += 32) {
            float e = __expf(sattn[q][w] - m);
            sattn[q][w] = e;
            ss += e;
        }
#pragma unroll
        for (int o = 16; o > 0; o >>= 1) ss += __shfl_xor_sync(0xffffffffu, ss, o);
        if (lane == 0) invs[w] = 1.f / ss;
    }
    __syncthreads();

    // phase B: thread = (d, row-group); each runs full jj range for 4 rows
    {
        const int d   = tid & 63;
        const int grp = tid >> 6;              // 0..3 -> rows grp*4 .. grp*4+3
        float a0 = 0.f, a1 = 0.f, a2 = 0.f, a3 = 0.f;
        for (int jj = 0; jj < span; ++jj) {
            const float vv = vw[jj][d];
            const float4 s = *(const float4*)&sattn[jj][grp * 4];
            a0 = fmaf(s.x, vv, a0);
            a1 = fmaf(s.y, vv, a1);
            a2 = fmaf(s.z, vv, a2);
            a3 = fmaf(s.w, vv, a3);
        }
        const float r0 = a0 * invs[grp * 4 + 0];
        const float r1 = a1 * invs[grp * 4 + 1];
        const float r2 = a2 * invs[grp * 4 + 2];
        const float r3 = a3 * invs[grp * 4 + 3];
        const size_t base = (size_t)(i0 + grp * 4) * DD + h * HDIM + d;
#pragma unroll
        for (int rI = 0; rI < 4; ++rI) {
            const float val = (rI == 0) ? r0 : (rI == 1) ? r1 : (rI == 2) ? r2 : r3;
            const size_t idx = base + (size_t)rI * DD;
            __nv_bfloat16 hv = __float2bfloat16(val);
            __nv_bfloat16 lv = __float2bfloat16(val - __bfloat162float(hv));
            oh_buf[idx] = hv;
            ol_buf[idx] = lv;
        }
    }
}

// ---------------- launch ---------------------------------------------------
extern "C" void kernel_launch(void* const* d_in, const int* in_sizes, int n_in,
                              void* d_out, int out_size)
{
    const float* x  = (const float*)d_in[0];
    const float* Wg = (const float*)d_in[1];
    const float* bg = (const float*)d_in[2];
    const float* Wv = (const float*)d_in[3];
    const float* bv = (const float*)d_in[4];
    const float* Wo = (const float*)d_in[5];
    const float* bo = (const float*)d_in[6];
    float* out = (float*)d_out;

    cudaFuncSetAttribute(k_gemm_gv,   cudaFuncAttributeMaxDynamicSharedMemorySize, SMEM_G);
    cudaFuncSetAttribute(k_gemm_o,    cudaFuncAttributeMaxDynamicSharedMemorySize, SMEM_G);
    cudaFuncSetAttribute(k_scores_mma,cudaFuncAttributeMaxDynamicSharedMemorySize, SMEM_S);
    cudaFuncSetAttribute(k_attnv,     cudaFuncAttributeMaxDynamicSharedMemorySize, ATTN_SMEM);

    k_conv_all<<<2560, 256>>>(x, Wg, Wv, Wo);                 // #1

    dim3 gemm_gv(DD / 64, TT / 128, 2);
    k_gemm_gv<<<gemm_gv, 256, SMEM_G>>>(bg, bv);              // #2

    dim3 sc_grid(TT / SIT, NH);
    k_scores_mma<<<sc_grid, 256, SMEM_S>>>();                 // #3

    dim3 av_grid(TT / IT, NH);
    k_attnv<<<av_grid, 256, ATTN_SMEM>>>();                   // #4 (ncu slot)

    dim3 gemm_o(DD / 64, TT / 128, 1);
    k_gemm_o<<<gemm_o, 256, SMEM_G>>>(bo, out);               // #5
}

// round 13
// speedup vs baseline: 1.2238x; 1.1626x over previous
#include <cuda_runtime.h>
#include <cuda_bf16.h>
#include <cuda_fp16.h>
#include <math.h>
#include <stdint.h>

#define TT   2048
#define DD   1024
#define NH   16
#define HDIM 64
#define WIN  128
#define PSTR 132
#define IT   16
#define JTA  148
#define SIT  64     // scores i-tile
#define SPAN 192    // scores j-window (64 + 128)

// ---------------- scratch (static device globals; no allocation) ----------
__device__ float v_buf[TT * DD];
__device__ float norm_buf[NH * TT];
__device__ float denom_buf[NH * TT];
__device__ float suminv_buf[NH];
__device__ float p_buf[(size_t)NH * TT * PSTR];

// fp16 GEMM operands: A-side split hi/lo, B-side (weights) single fp16
__device__ __half xh_buf[TT * DD], xl_buf[TT * DD];
__device__ __half oh_buf[TT * DD], ol_buf[TT * DD];
__device__ __half wgh_buf[DD * DD], wvh_buf[DD * DD], woh_buf[DD * DD];
// bf16 hi/lo of g for the (precision-sensitive) scores kernel
__device__ __nv_bfloat16 gh_buf[TT * DD], gl_buf[TT * DD];

// ---------------- PTX helpers ----------------------------------------------
__device__ __forceinline__ uint32_t s2u(const void* p) {
    uint32_t a;
    asm("{ .reg .u64 t; cvta.to.shared.u64 t, %1; cvt.u32.u64 %0, t; }"
        : "=r"(a) : "l"(p));
    return a;
}
#define CP_ASYNC16(dst, src) \
    asm volatile("cp.async.cg.shared.global [%0], [%1], 16;" :: "r"(dst), "l"(src))
#define CP_COMMIT()  asm volatile("cp.async.commit_group;" ::: "memory")
#define CP_WAIT2()   asm volatile("cp.async.wait_group 2;" ::: "memory")
#define CP_WAIT1()   asm volatile("cp.async.wait_group 1;" ::: "memory")
#define CP_WAIT0()   asm volatile("cp.async.wait_group 0;" ::: "memory")

__device__ __forceinline__ void ldsm_x4(uint32_t& r0, uint32_t& r1,
                                        uint32_t& r2, uint32_t& r3, uint32_t a) {
    asm volatile("ldmatrix.sync.aligned.m8n8.x4.shared.b16 {%0,%1,%2,%3}, [%4];"
                 : "=r"(r0), "=r"(r1), "=r"(r2), "=r"(r3) : "r"(a));
}
// bf16 mma (scores)
__device__ __forceinline__ void mma16816(float* d, const uint32_t* a, const uint32_t* b) {
    asm volatile(
        "mma.sync.aligned.m16n8k16.row.col.f32.bf16.bf16.f32 "
        "{%0,%1,%2,%3}, {%4,%5,%6,%7}, {%8,%9}, {%0,%1,%2,%3};"
        : "+f"(d[0]), "+f"(d[1]), "+f"(d[2]), "+f"(d[3])
        : "r"(a[0]), "r"(a[1]), "r"(a[2]), "r"(a[3]), "r"(b[0]), "r"(b[1]));
}
// fp16 mma (GEMMs)
__device__ __forceinline__ void mma16816h(float* d, const uint32_t* a, const uint32_t* b) {
    asm volatile(
        "mma.sync.aligned.m16n8k16.row.col.f32.f16.f16.f32 "
        "{%0,%1,%2,%3}, {%4,%5,%6,%7}, {%8,%9}, {%0,%1,%2,%3};"
        : "+f"(d[0]), "+f"(d[1]), "+f"(d[2]), "+f"(d[3])
        : "r"(a[0]), "r"(a[1]), "r"(a[2]), "r"(a[3]), "r"(b[0]), "r"(b[1]));
}
__device__ __forceinline__ uint32_t sw64(uint32_t off) {
    return off ^ ((off >> 3) & 0x30u);
}
__device__ __forceinline__ uint32_t sw128(uint32_t off) {
    return off ^ ((off >> 3) & 0x70u);
}

// ---------------- conversions ------------------------------------------------
// fp32 -> fp16 hi/lo split (A operands)
__device__ __forceinline__ void split_store_h(const float* __restrict__ src,
                                              __half* __restrict__ dh,
                                              __half* __restrict__ dl, int i)
{
    float4 v = ((const float4*)src)[i];
    __half h0 = __float2half_rn(v.x), h1 = __float2half_rn(v.y),
           h2 = __float2half_rn(v.z), h3 = __float2half_rn(v.w);
    __half l0 = __float2half_rn(v.x - __half2float(h0)),
           l1 = __float2half_rn(v.y - __half2float(h1)),
           l2 = __float2half_rn(v.z - __half2float(h2)),
           l3 = __float2half_rn(v.w - __half2float(h3));
    __half2 hp0(h0, h1), hp1(h2, h3), lp0(l0, l1), lp1(l2, l3);
    uint2 uh, ul;
    uh.x = *(unsigned*)&hp0; uh.y = *(unsigned*)&hp1;
    ul.x = *(unsigned*)&lp0; ul.y = *(unsigned*)&lp1;
    ((uint2*)dh)[i] = uh;
    ((uint2*)dl)[i] = ul;
}
// fp32 -> single fp16 (B operands / weights)
__device__ __forceinline__ void single_store_h(const float* __restrict__ src,
                                               __half* __restrict__ dh, int i)
{
    float4 v = ((const float4*)src)[i];
    __half2 hp0(__float2half_rn(v.x), __float2half_rn(v.y));
    __half2 hp1(__float2half_rn(v.z), __float2half_rn(v.w));
    uint2 uh;
    uh.x = *(unsigned*)&hp0; uh.y = *(unsigned*)&hp1;
    ((uint2*)dh)[i] = uh;
}

__global__ void __launch_bounds__(256)
k_conv_all(const float* __restrict__ x,  const float* __restrict__ Wg,
           const float* __restrict__ Wv, const float* __restrict__ Wo)
{
    const int b = blockIdx.x;
    if (b == 0 && threadIdx.x < NH) suminv_buf[threadIdx.x] = 0.f;
    if (b < 1024) {                       // x: hi/lo split
        const int i = b * 512 + threadIdx.x;
        split_store_h(x, xh_buf, xl_buf, i);
        split_store_h(x, xh_buf, xl_buf, i + 256);
    } else if (b < 1536) {                // Wg: single fp16
        const int i = (b - 1024) * 512 + threadIdx.x;
        single_store_h(Wg, wgh_buf, i);
        single_store_h(Wg, wgh_buf, i + 256);
    } else if (b < 2048) {                // Wv
        const int i = (b - 1536) * 512 + threadIdx.x;
        single_store_h(Wv, wvh_buf, i);
        single_store_h(Wv, wvh_buf, i + 256);
    } else {                              // Wo
        const int i = (b - 2048) * 512 + threadIdx.x;
        single_store_h(Wo, woh_buf, i);
        single_store_h(Wo, woh_buf, i + 256);
    }
}

// ---------------- fp16 2-product GEMM: C = (Ah+Al)[M,K] * Bh[N,K]^T + bias ---
#define KC32   32
#define NC     (DD / KC32)
#define ATSZ   8192                 // 128 rows x 64B
#define BTSZ   4096                 // 64 rows x 64B
#define STG    (2 * ATSZ + BTSZ)    // Ah, Al, Bh = 20480
#define NSTAGE 4
#define SMEM_G (NSTAGE * STG)       // 81920

__device__ __forceinline__ void load_stage(
    const uint4* __restrict__ Ah4, const uint4* __restrict__ Al4,
    const uint4* __restrict__ Bh4,
    uint32_t sb, int slot, int c, int m0, int n0, int tid)
{
    const uint32_t base = sb + slot * STG;
    const int q = tid & 3;
#pragma unroll
    for (int t = 0; t < 4; ++t) {       // t<2: Ah rows, t>=2: Al rows
        const int row = (t * 64 + (tid >> 2)) & 127;
        const uint32_t dst = base + (t >> 1) * ATSZ + sw64((uint32_t)row * 64u + q * 16u);
        const uint4* src = ((t >> 1) ? Al4 : Ah4)
                         + (size_t)(m0 + row) * (DD / 8) + c * 4 + q;
        CP_ASYNC16(dst, src);
    }
    {                                   // Bh (single tile)
        const int row = tid >> 2;
        const uint32_t dst = base + 2 * ATSZ + sw64((uint32_t)row * 64u + q * 16u);
        const uint4* src = Bh4 + (size_t)(n0 + row) * (DD / 8) + c * 4 + q;
        CP_ASYNC16(dst, src);
    }
}

__device__ __forceinline__ void gemm_core(
    const uint4* __restrict__ Ah4, const uint4* __restrict__ Al4,
    const uint4* __restrict__ Bh4,
    const float* __restrict__ bias, float* __restrict__ C, bool doNorm)
{
    extern __shared__ char smem[];
    __shared__ float ssrow[128];
    const uint32_t sb = s2u(smem);
    const int tid  = threadIdx.x;
    const int wid  = tid >> 5;
    const int lane = tid & 31;
    const int n0 = blockIdx.x * 64, m0 = blockIdx.y * 128;

    const int wm = wid >> 1;
    const int wn = wid & 1;

    const int r  = lane & 7;
    const int md = lane >> 3;
    const int rowA = wm * 32 + (md & 1) * 8 + r;
    const uint32_t bA = (md >> 1) * 16;
    const int rowB = wn * 32 + (md >> 1) * 8 + r;
    const uint32_t bB = (md & 1) * 16;

    if (doNorm && tid < 128) ssrow[tid] = 0.f;

    float acc[2][4][4];
#pragma unroll
    for (int f = 0; f < 2; ++f)
#pragma unroll
        for (int j = 0; j < 4; ++j)
#pragma unroll
            for (int e = 0; e < 4; ++e) acc[f][j][e] = 0.f;

    load_stage(Ah4, Al4, Bh4, sb, 0, 0, m0, n0, tid); CP_COMMIT();
    load_stage(Ah4, Al4, Bh4, sb, 1, 1, m0, n0, tid); CP_COMMIT();
    load_stage(Ah4, Al4, Bh4, sb, 2, 2, m0, n0, tid); CP_COMMIT();

#pragma unroll 1
    for (int c = 0; c < NC; ++c) {
        const int rem = NC - 1 - c;
        if (rem >= 2) CP_WAIT2(); else if (rem == 1) CP_WAIT1(); else CP_WAIT0();
        __syncthreads();

        const uint32_t base = sb + (c & 3) * STG;
        const uint32_t stAh = base;
        const uint32_t stAl = base + ATSZ;
        const uint32_t stBh = base + 2 * ATSZ;

#pragma unroll
        for (int ks = 0; ks < 2; ++ks) {
            const uint32_t kb = ks * 32;
            uint32_t ah[2][4], al[2][4];
#pragma unroll
            for (int f = 0; f < 2; ++f) {
                const uint32_t off = sw64((uint32_t)(rowA + f * 16) * 64u + kb + bA);
                ldsm_x4(ah[f][0], ah[f][1], ah[f][2], ah[f][3], stAh + off);
                ldsm_x4(al[f][0], al[f][1], al[f][2], al[f][3], stAl + off);
            }
            uint32_t bh[4][2];
#pragma unroll
            for (int p = 0; p < 2; ++p) {
                const uint32_t off = sw64((uint32_t)(rowB + p * 16) * 64u + kb + bB);
                ldsm_x4(bh[2*p][0], bh[2*p][1], bh[2*p+1][0], bh[2*p+1][1], stBh + off);
            }
#pragma unroll
            for (int f = 0; f < 2; ++f)
#pragma unroll
                for (int j = 0; j < 4; ++j) {
                    mma16816h(acc[f][j], ah[f], bh[j]);
                    mma16816h(acc[f][j], al[f], bh[j]);
                }
        }
        if (c + 3 < NC) {
            load_stage(Ah4, Al4, Bh4, sb, (c + 3) & 3, c + 3, m0, n0, tid);
            CP_COMMIT();
        }
    }

    // epilogue
#pragma unroll
    for (int f = 0; f < 2; ++f) {
        const int grow = m0 + wm * 32 + f * 16 + (lane >> 2);
        float ss0 = 0.f, ss1 = 0.f;
#pragma unroll
        for (int j = 0; j < 4; ++j) {
            const int col = n0 + wn * 32 + j * 8 + (lane & 3) * 2;
            const float2 bb = *(const float2*)(bias + col);
            float2 o0 = make_float2(acc[f][j][0] + bb.x, acc[f][j][1] + bb.y);
            float2 o1 = make_float2(acc[f][j][2] + bb.x, acc[f][j][3] + bb.y);
            if (doNorm) {
                // g: bf16 hi/lo split store (feeds scores mma)
                const size_t p0 = ((size_t)grow * DD + col) >> 1;
                const size_t p1 = ((size_t)(grow + 8) * DD + col) >> 1;
                __nv_bfloat16 h00 = __float2bfloat16(o0.x), h01 = __float2bfloat16(o0.y);
                __nv_bfloat16 h10 = __float2bfloat16(o1.x), h11 = __float2bfloat16(o1.y);
                __nv_bfloat16 l00 = __float2bfloat16(o0.x - __bfloat162float(h00));
                __nv_bfloat16 l01 = __float2bfloat16(o0.y - __bfloat162float(h01));
                __nv_bfloat16 l10 = __float2bfloat16(o1.x - __bfloat162float(h10));
                __nv_bfloat16 l11 = __float2bfloat16(o1.y - __bfloat162float(h11));
                ((__nv_bfloat162*)gh_buf)[p0] = __nv_bfloat162(h00, h01);
                ((__nv_bfloat162*)gl_buf)[p0] = __nv_bfloat162(l00, l01);
                ((__nv_bfloat162*)gh_buf)[p1] = __nv_bfloat162(h10, h11);
                ((__nv_bfloat162*)gl_buf)[p1] = __nv_bfloat162(l10, l11);
                ss0 = fmaf(o0.x, o0.x, fmaf(o0.y, o0.y, ss0));
                ss1 = fmaf(o1.x, o1.x, fmaf(o1.y, o1.y, ss1));
            } else {
                float* c0 = C + (size_t)grow * DD;
                *(float2*)(c0 + col) = o0;
                *(float2*)(c0 + 8 * DD + col) = o1;
            }
        }
        if (doNorm) {
            ss0 += __shfl_xor_sync(0xffffffffu, ss0, 1);
            ss0 += __shfl_xor_sync(0xffffffffu, ss0, 2);
            ss1 += __shfl_xor_sync(0xffffffffu, ss1, 1);
            ss1 += __shfl_xor_sync(0xffffffffu, ss1, 2);
            if ((lane & 3) == 0) {
                const int l0 = wm * 32 + f * 16 + (lane >> 2);
                atomicAdd(&ssrow[l0], ss0);
                atomicAdd(&ssrow[l0 + 8], ss1);
            }
        }
    }
    if (doNorm) {
        __syncthreads();
        if (tid < 128) {
            const int h = n0 >> 6;
            norm_buf[h * TT + m0 + tid] = sqrtf(ssrow[tid]);
        }
    }
}

__global__ void __launch_bounds__(256, 2)
k_gemm_gv(const float* __restrict__ bg, const float* __restrict__ bv)
{
    if (blockIdx.z == 0)
        gemm_core((const uint4*)xh_buf, (const uint4*)xl_buf,
                  (const uint4*)wgh_buf, bg, nullptr, true);
    else
        gemm_core((const uint4*)xh_buf, (const uint4*)xl_buf,
                  (const uint4*)wvh_buf, bv, v_buf, false);
}

__global__ void __launch_bounds__(256, 2)
k_gemm_o(const float* __restrict__ bo, float* __restrict__ out)
{
    gemm_core((const uint4*)oh_buf, (const uint4*)ol_buf,
              (const uint4*)woh_buf, bo, out, false);
}

// ---------------- MMA banded scores (bf16 3-product, unchanged) --------------
#define WTSZ   (SPAN * 128)
#define SMEM_S (2 * WTSZ)

__global__ void __launch_bounds__(256)
k_scores_mma()
{
    extern __shared__ char smem[];
    __shared__ float nwin[SPAN];
    __shared__ float rowsum[SIT];
    __shared__ float sinv[SIT];

    const uint32_t sbH = s2u(smem);
    const uint32_t sbL = sbH + WTSZ;
    const int tid  = threadIdx.x;
    const int wid  = tid >> 5;
    const int lane = tid & 31;
    const int i0 = blockIdx.x * SIT;
    const int h  = blockIdx.y;

    const int jstart0 = (i0 > WIN) ? (i0 - WIN) : 0;
    const int qbase   = i0 - jstart0;

    const uint4* gh4 = (const uint4*)gh_buf;
    const uint4* gl4 = (const uint4*)gl_buf;
#pragma unroll
    for (int t = 0; t < 6; ++t) {
        const int idx = t * 256 + tid;
        const int row = idx >> 3;
        const int q   = idx & 7;
        const uint32_t d = sw128((uint32_t)row * 128u + q * 16u);
        const size_t g = (size_t)(jstart0 + row) * (DD / 8) + h * 8 + q;
        CP_ASYNC16(sbH + d, gh4 + g);
        CP_ASYNC16(sbL + d, gl4 + g);
    }
    CP_COMMIT();
    if (tid < SPAN) nwin[tid] = norm_buf[h * TT + jstart0 + tid];
    if (tid < SIT) rowsum[tid] = 0.f;
    CP_WAIT0();
    __syncthreads();

    const int wm = wid >> 1;
    const int wn = wid & 1;

    const int r  = lane & 7;
    const int md = lane >> 3;
    const int arow  = qbase + wm * 16 + (md & 1) * 8 + r;
    const uint32_t abyte = (md >> 1) * 16;
    const int brow0 = wn * 96 + (md >> 1) * 8 + r;
    const uint32_t bbyte = (md & 1) * 16;

    float acc[12][4];
#pragma unroll
    for (int nt = 0; nt < 12; ++nt)
#pragma unroll
        for (int e = 0; e < 4; ++e) acc[nt][e] = 0.f;

#pragma unroll
    for (int ks = 0; ks < 4; ++ks) {
        const uint32_t kb = ks * 32;
        uint32_t ah[4], al[4];
        const uint32_t aoff = sw128((uint32_t)arow * 128u + kb + abyte);
        ldsm_x4(ah[0], ah[1], ah[2], ah[3], sbH + aoff);
        ldsm_x4(al[0], al[1], al[2], al[3], sbL + aoff);
#pragma unroll
        for (int bt = 0; bt < 6; ++bt) {
            uint32_t bh[2][2], bl[2][2];
            const uint32_t boff = sw128((uint32_t)(brow0 + bt * 16) * 128u + kb + bbyte);
            ldsm_x4(bh[0][0], bh[0][1], bh[1][0], bh[1][1], sbH + boff);
            ldsm_x4(bl[0][0], bl[0][1], bl[1][0], bl[1][1], sbL + boff);
#pragma unroll
            for (int p = 0; p < 2; ++p) {
                mma16816(acc[2*bt + p], ah, bh[p]);
                mma16816(acc[2*bt + p], ah, bl[p]);
                mma16816(acc[2*bt + p], al, bh[p]);
            }
        }
    }

    const int quad = lane >> 2;
    const int cp2  = (lane & 3) * 2;
    const int gi0 = i0 + wm * 16 + quad;
    const int gi1 = gi0 + 8;
    const float ni0 = nwin[qbase + wm * 16 + quad];
    const float ni1 = nwin[qbase + wm * 16 + quad + 8];
    const int off0 = (gi0 > WIN) ? (gi0 - WIN) : 0;
    const int off1 = (gi1 > WIN) ? (gi1 - WIN) : 0;
    float* pr0 = p_buf + (size_t)(h * TT + gi0) * PSTR;
    float* pr1 = p_buf + (size_t)(h * TT + gi1) * PSTR;
    float ps0 = 0.f, ps1 = 0.f;

#pragma unroll
    for (int nt = 0; nt < 12; ++nt) {
        const int jl = wn * 96 + nt * 8 + cp2;
        const int jg = jstart0 + jl;
        const float nj0 = nwin[jl];
        const float nj1 = nwin[jl + 1];
#pragma unroll
        for (int e = 0; e < 4; ++e) {
            const int  jj = jg + (e & 1);
            const float nj = (e & 1) ? nj1 : nj0;
            const int  gi  = (e >> 1) ? gi1 : gi0;
            const float ni = (e >> 1) ? ni1 : ni0;
            const int  off = (e >> 1) ? off1 : off0;
            if (jj <= gi && jj >= off) {
                float c = acc[nt][e] / (ni * nj + 1e-8f);
                if (c != c) c = 0.f;
                float p = (c + 1.f) * 0.5f;
                ((e >> 1) ? pr1 : pr0)[jj - off] = p;
                if (e >> 1) ps1 += p; else ps0 += p;
            }
        }
    }

    ps0 += __shfl_xor_sync(0xffffffffu, ps0, 1);
    ps0 += __shfl_xor_sync(0xffffffffu, ps0, 2);
    ps1 += __shfl_xor_sync(0xffffffffu, ps1, 1);
    ps1 += __shfl_xor_sync(0xffffffffu, ps1, 2);
    if ((lane & 3) == 0) {
        atomicAdd(&rowsum[wm * 16 + quad], ps0);
        atomicAdd(&rowsum[wm * 16 + quad + 8], ps1);
    }
    __syncthreads();

    if (tid < SIT) {
        const int i   = i0 + tid;
        const int cnt = i - ((i > WIN) ? (i - WIN) : 0) + 1;
        float gm = (rowsum[tid] + 0.5f * (float)(TT - cnt)) * (1.f / (float)TT);
        float dn = gm + 0.5f;
        denom_buf[h * TT + i] = dn;
        sinv[tid] = 1.f / dn;
    }
    __syncthreads();
    if (tid < 32) {
        float s = sinv[tid] + sinv[tid + 32];
#pragma unroll
        for (int o = 16; o > 0; o >>= 1) s += __shfl_xor_sync(0xffffffffu, s, o);
        if (tid == 0) atomicAdd(&suminv_buf[h], s);
    }
}

// ---------------- softmax + attn@v (16 rows / block), emits fp16 hi/lo ------
#define SATT_STRIDE 20
#define ATTN_SMEM   (JTA * HDIM * 4 + JTA * SATT_STRIDE * 4 + 64)

__global__ void __launch_bounds__(256)
k_attnv()
{
    extern __shared__ char dynsm[];
    float (*vw)[HDIM]       = (float(*)[HDIM])dynsm;                 // [JTA][64]
    float (*sattn)[SATT_STRIDE] =
        (float(*)[SATT_STRIDE])(dynsm + JTA * HDIM * 4);             // [JTA][20]
    float* invs = (float*)(dynsm + JTA * HDIM * 4 + JTA * SATT_STRIDE * 4); // [16]

    const int i0  = blockIdx.x * IT;
    const int h   = blockIdx.y;
    const int tid = threadIdx.x;
    const int wid = tid >> 5;
    const int lane = tid & 31;

    const int jstart0 = (i0 > WIN) ? (i0 - WIN) : 0;
    const int span    = (i0 + IT - 1) - jstart0 + 1;

    const float4* v4 = (const float4*)v_buf;
    for (int idx = tid; idx < span * 16; idx += 256) {
        int jj = idx >> 4;
        int q  = idx & 15;
        ((float4*)&vw[jj][0])[q] = v4[(size_t)(jstart0 + jj) * (DD / 4) + h * (HDIM / 4) + q];
    }
    __syncthreads();

#pragma unroll
    for (int rr = 0; rr < 2; ++rr) {
        const int w = wid + rr * 8;
        const int i = i0 + w;
        const size_t row = (size_t)h * TT + i;
        const float fit  = 1.f / (denom_buf[row] * suminv_buf[h]);
        const int off = ((i > WIN) ? (i - WIN) : 0) - jstart0;
        const int wi  = i - jstart0;

        float m = -1e30f;
        for (int q = lane; q < JTA; q += 32) {
            bool in = (q >= off) && (q <= wi);
            float s = in ? fit * p_buf[row * PSTR + (q - off)] : -1e30f;
            sattn[q][w] = s;
            m = fmaxf(m, s);
        }
#pragma unroll
        for (int o = 16; o > 0; o >>= 1) m = fmaxf(m, __shfl_xor_sync(0xffffffffu, m, o));

        float ss = 0.f;
        for (int q = lane; q < JTA; q += 32) {
            float e = __expf(sattn[q][w] - m);
            sattn[q][w] = e;
            ss += e;
        }
#pragma unroll
        for (int o = 16; o > 0; o >>= 1) ss += __shfl_xor_sync(0xffffffffu, ss, o);
        if (lane == 0) invs[w] = 1.f / ss;
    }
    __syncthreads();

    // phase B: thread = (d, row-group); each runs full jj range for 4 rows
    {
        const int d   = tid & 63;
        const int grp = tid >> 6;
        float a0 = 0.f, a1 = 0.f, a2 = 0.f, a3 = 0.f;
        for (int jj = 0; jj < span; ++jj) {
            const float vv = vw[jj][d];
            const float4 s = *(const float4*)&sattn[jj][grp * 4];
            a0 = fmaf(s.x, vv, a0);
            a1 = fmaf(s.y, vv, a1);
            a2 = fmaf(s.z, vv, a2);
            a3 = fmaf(s.w, vv, a3);
        }
        const float r0 = a0 * invs[grp * 4 + 0];
        const float r1 = a1 * invs[grp * 4 + 1];
        const float r2 = a2 * invs[grp * 4 + 2];
        const float r3 = a3 * invs[grp * 4 + 3];
        const size_t base = (size_t)(i0 + grp * 4) * DD + h * HDIM + d;
#pragma unroll
        for (int rI = 0; rI < 4; ++rI) {
            const float val = (rI == 0) ? r0 : (rI == 1) ? r1 : (rI == 2) ? r2 : r3;
            const size_t idx = base + (size_t)rI * DD;
            __half hv = __float2half_rn(val);
            __half lv = __float2half_rn(val - __half2float(hv));
            oh_buf[idx] = hv;
            ol_buf[idx] = lv;
        }
    }
}

// ---------------- launch ---------------------------------------------------
extern "C" void kernel_launch(void* const* d_in, const int* in_sizes, int n_in,
                              void* d_out, int out_size)
{
    const float* x  = (const float*)d_in[0];
    const float* Wg = (const float*)d_in[1];
    const float* bg = (const float*)d_in[2];
    const float* Wv = (const float*)d_in[3];
    const float* bv = (const float*)d_in[4];
    const float* Wo = (const float*)d_in[5];
    const float* bo = (const float*)d_in[6];
    float* out = (float*)d_out;

    cudaFuncSetAttribute(k_gemm_gv,   cudaFuncAttributeMaxDynamicSharedMemorySize, SMEM_G);
    cudaFuncSetAttribute(k_gemm_o,    cudaFuncAttributeMaxDynamicSharedMemorySize, SMEM_G);
    cudaFuncSetAttribute(k_scores_mma,cudaFuncAttributeMaxDynamicSharedMemorySize, SMEM_S);
    cudaFuncSetAttribute(k_attnv,     cudaFuncAttributeMaxDynamicSharedMemorySize, ATTN_SMEM);

    k_conv_all<<<2560, 256>>>(x, Wg, Wv, Wo);                 // #1

    dim3 gemm_gv(DD / 64, TT / 128, 2);
    k_gemm_gv<<<gemm_gv, 256, SMEM_G>>>(bg, bv);              // #2

    dim3 sc_grid(TT / SIT, NH);
    k_scores_mma<<<sc_grid, 256, SMEM_S>>>();                 // #3

    dim3 av_grid(TT / IT, NH);
    k_attnv<<<av_grid, 256, ATTN_SMEM>>>();                   // #4 (ncu slot)

    dim3 gemm_o(DD / 64, TT / 128, 1);
    k_gemm_o<<<gemm_o, 256, SMEM_G>>>(bo, out);               // #5
}

// round 14
// speedup vs baseline: 1.2711x; 1.0386x over previous
#include <cuda_runtime.h>
#include <cuda_bf16.h>
#include <cuda_fp16.h>
#include <math.h>
#include <stdint.h>

#define TT   2048
#define DD   1024
#define NH   16
#define HDIM 64
#define WIN  128
#define PSTR 132
#define IT   16
#define JTA  148
#define SIT  64     // scores i-tile
#define SPAN 192    // scores j-window (64 + 128)

// ---------------- scratch (static device globals; no allocation) ----------
__device__ float v_buf[TT * DD];
__device__ float norm_buf[NH * TT];
__device__ float denom_buf[NH * TT];
__device__ float suminv_buf[NH];
__device__ __half p_buf[(size_t)NH * TT * PSTR];   // fp16 score matrix

// fp16 GEMM operands: A-side split hi/lo, B-side (weights) single fp16
__device__ __half xh_buf[TT * DD], xl_buf[TT * DD];
__device__ __half oh_buf[TT * DD], ol_buf[TT * DD];
__device__ __half wgh_buf[DD * DD], wvh_buf[DD * DD], woh_buf[DD * DD];
// bf16 hi/lo of g for the (precision-sensitive) scores kernel
__device__ __nv_bfloat16 gh_buf[TT * DD], gl_buf[TT * DD];

// ---------------- PTX helpers ----------------------------------------------
__device__ __forceinline__ uint32_t s2u(const void* p) {
    uint32_t a;
    asm("{ .reg .u64 t; cvta.to.shared.u64 t, %1; cvt.u32.u64 %0, t; }"
        : "=r"(a) : "l"(p));
    return a;
}
#define CP_ASYNC16(dst, src) \
    asm volatile("cp.async.cg.shared.global [%0], [%1], 16;" :: "r"(dst), "l"(src))
#define CP_COMMIT()  asm volatile("cp.async.commit_group;" ::: "memory")
#define CP_WAIT2()   asm volatile("cp.async.wait_group 2;" ::: "memory")
#define CP_WAIT1()   asm volatile("cp.async.wait_group 1;" ::: "memory")
#define CP_WAIT0()   asm volatile("cp.async.wait_group 0;" ::: "memory")

__device__ __forceinline__ void ldsm_x4(uint32_t& r0, uint32_t& r1,
                                        uint32_t& r2, uint32_t& r3, uint32_t a) {
    asm volatile("ldmatrix.sync.aligned.m8n8.x4.shared.b16 {%0,%1,%2,%3}, [%4];"
                 : "=r"(r0), "=r"(r1), "=r"(r2), "=r"(r3) : "r"(a));
}
// bf16 mma (scores)
__device__ __forceinline__ void mma16816(float* d, const uint32_t* a, const uint32_t* b) {
    asm volatile(
        "mma.sync.aligned.m16n8k16.row.col.f32.bf16.bf16.f32 "
        "{%0,%1,%2,%3}, {%4,%5,%6,%7}, {%8,%9}, {%0,%1,%2,%3};"
        : "+f"(d[0]), "+f"(d[1]), "+f"(d[2]), "+f"(d[3])
        : "r"(a[0]), "r"(a[1]), "r"(a[2]), "r"(a[3]), "r"(b[0]), "r"(b[1]));
}
// fp16 mma (GEMMs)
__device__ __forceinline__ void mma16816h(float* d, const uint32_t* a, const uint32_t* b) {
    asm volatile(
        "mma.sync.aligned.m16n8k16.row.col.f32.f16.f16.f32 "
        "{%0,%1,%2,%3}, {%4,%5,%6,%7}, {%8,%9}, {%0,%1,%2,%3};"
        : "+f"(d[0]), "+f"(d[1]), "+f"(d[2]), "+f"(d[3])
        : "r"(a[0]), "r"(a[1]), "r"(a[2]), "r"(a[3]), "r"(b[0]), "r"(b[1]));
}
__device__ __forceinline__ uint32_t sw64(uint32_t off) {
    return off ^ ((off >> 3) & 0x30u);
}
__device__ __forceinline__ uint32_t sw128(uint32_t off) {
    return off ^ ((off >> 3) & 0x70u);
}

// ---------------- conversions ------------------------------------------------
__device__ __forceinline__ void split_store_h(const float* __restrict__ src,
                                              __half* __restrict__ dh,
                                              __half* __restrict__ dl, int i)
{
    float4 v = ((const float4*)src)[i];
    __half h0 = __float2half_rn(v.x), h1 = __float2half_rn(v.y),
           h2 = __float2half_rn(v.z), h3 = __float2half_rn(v.w);
    __half l0 = __float2half_rn(v.x - __half2float(h0)),
           l1 = __float2half_rn(v.y - __half2float(h1)),
           l2 = __float2half_rn(v.z - __half2float(h2)),
           l3 = __float2half_rn(v.w - __half2float(h3));
    __half2 hp0(h0, h1), hp1(h2, h3), lp0(l0, l1), lp1(l2, l3);
    uint2 uh, ul;
    uh.x = *(unsigned*)&hp0; uh.y = *(unsigned*)&hp1;
    ul.x = *(unsigned*)&lp0; ul.y = *(unsigned*)&lp1;
    ((uint2*)dh)[i] = uh;
    ((uint2*)dl)[i] = ul;
}
__device__ __forceinline__ void single_store_h(const float* __restrict__ src,
                                               __half* __restrict__ dh, int i)
{
    float4 v = ((const float4*)src)[i];
    __half2 hp0(__float2half_rn(v.x), __float2half_rn(v.y));
    __half2 hp1(__float2half_rn(v.z), __float2half_rn(v.w));
    uint2 uh;
    uh.x = *(unsigned*)&hp0; uh.y = *(unsigned*)&hp1;
    ((uint2*)dh)[i] = uh;
}

__global__ void __launch_bounds__(256)
k_conv_all(const float* __restrict__ x,  const float* __restrict__ Wg,
           const float* __restrict__ Wv, const float* __restrict__ Wo)
{
    const int b = blockIdx.x;
    if (b == 0 && threadIdx.x < NH) suminv_buf[threadIdx.x] = 0.f;
    if (b < 1024) {
        const int i = b * 512 + threadIdx.x;
        split_store_h(x, xh_buf, xl_buf, i);
        split_store_h(x, xh_buf, xl_buf, i + 256);
    } else if (b < 1536) {
        const int i = (b - 1024) * 512 + threadIdx.x;
        single_store_h(Wg, wgh_buf, i);
        single_store_h(Wg, wgh_buf, i + 256);
    } else if (b < 2048) {
        const int i = (b - 1536) * 512 + threadIdx.x;
        single_store_h(Wv, wvh_buf, i);
        single_store_h(Wv, wvh_buf, i + 256);
    } else {
        const int i = (b - 2048) * 512 + threadIdx.x;
        single_store_h(Wo, woh_buf, i);
        single_store_h(Wo, woh_buf, i + 256);
    }
}

// ---------------- fp16 2-product GEMM: C = (Ah+Al)[M,K] * Bh[N,K]^T + bias ---
#define KC32   32
#define NC     (DD / KC32)
#define ATSZ   8192
#define BTSZ   4096
#define STG    (2 * ATSZ + BTSZ)
#define NSTAGE 4
#define SMEM_G (NSTAGE * STG)       // 81920

__device__ __forceinline__ void load_stage(
    const uint4* __restrict__ Ah4, const uint4* __restrict__ Al4,
    const uint4* __restrict__ Bh4,
    uint32_t sb, int slot, int c, int m0, int n0, int tid)
{
    const uint32_t base = sb + slot * STG;
    const int q = tid & 3;
#pragma unroll
    for (int t = 0; t < 4; ++t) {
        const int row = (t * 64 + (tid >> 2)) & 127;
        const uint32_t dst = base + (t >> 1) * ATSZ + sw64((uint32_t)row * 64u + q * 16u);
        const uint4* src = ((t >> 1) ? Al4 : Ah4)
                         + (size_t)(m0 + row) * (DD / 8) + c * 4 + q;
        CP_ASYNC16(dst, src);
    }
    {
        const int row = tid >> 2;
        const uint32_t dst = base + 2 * ATSZ + sw64((uint32_t)row * 64u + q * 16u);
        const uint4* src = Bh4 + (size_t)(n0 + row) * (DD / 8) + c * 4 + q;
        CP_ASYNC16(dst, src);
    }
}

__device__ __forceinline__ void gemm_core(
    const uint4* __restrict__ Ah4, const uint4* __restrict__ Al4,
    const uint4* __restrict__ Bh4,
    const float* __restrict__ bias, float* __restrict__ C, bool doNorm)
{
    extern __shared__ char smem[];
    __shared__ float ssrow[128];
    const uint32_t sb = s2u(smem);
    const int tid  = threadIdx.x;
    const int wid  = tid >> 5;
    const int lane = tid & 31;
    const int n0 = blockIdx.x * 64, m0 = blockIdx.y * 128;

    const int wm = wid >> 1;
    const int wn = wid & 1;

    const int r  = lane & 7;
    const int md = lane >> 3;
    const int rowA = wm * 32 + (md & 1) * 8 + r;
    const uint32_t bA = (md >> 1) * 16;
    const int rowB = wn * 32 + (md >> 1) * 8 + r;
    const uint32_t bB = (md & 1) * 16;

    if (doNorm && tid < 128) ssrow[tid] = 0.f;

    float acc[2][4][4];
#pragma unroll
    for (int f = 0; f < 2; ++f)
#pragma unroll
        for (int j = 0; j < 4; ++j)
#pragma unroll
            for (int e = 0; e < 4; ++e) acc[f][j][e] = 0.f;

    load_stage(Ah4, Al4, Bh4, sb, 0, 0, m0, n0, tid); CP_COMMIT();
    load_stage(Ah4, Al4, Bh4, sb, 1, 1, m0, n0, tid); CP_COMMIT();
    load_stage(Ah4, Al4, Bh4, sb, 2, 2, m0, n0, tid); CP_COMMIT();

#pragma unroll 1
    for (int c = 0; c < NC; ++c) {
        const int rem = NC - 1 - c;
        if (rem >= 2) CP_WAIT2(); else if (rem == 1) CP_WAIT1(); else CP_WAIT0();
        __syncthreads();

        const uint32_t base = sb + (c & 3) * STG;
        const uint32_t stAh = base;
        const uint32_t stAl = base + ATSZ;
        const uint32_t stBh = base + 2 * ATSZ;

#pragma unroll
        for (int ks = 0; ks < 2; ++ks) {
            const uint32_t kb = ks * 32;
            uint32_t ah[2][4], al[2][4];
#pragma unroll
            for (int f = 0; f < 2; ++f) {
                const uint32_t off = sw64((uint32_t)(rowA + f * 16) * 64u + kb + bA);
                ldsm_x4(ah[f][0], ah[f][1], ah[f][2], ah[f][3], stAh + off);
                ldsm_x4(al[f][0], al[f][1], al[f][2], al[f][3], stAl + off);
            }
            uint32_t bh[4][2];
#pragma unroll
            for (int p = 0; p < 2; ++p) {
                const uint32_t off = sw64((uint32_t)(rowB + p * 16) * 64u + kb + bB);
                ldsm_x4(bh[2*p][0], bh[2*p][1], bh[2*p+1][0], bh[2*p+1][1], stBh + off);
            }
#pragma unroll
            for (int f = 0; f < 2; ++f)
#pragma unroll
                for (int j = 0; j < 4; ++j) {
                    mma16816h(acc[f][j], ah[f], bh[j]);
                    mma16816h(acc[f][j], al[f], bh[j]);
                }
        }
        if (c + 3 < NC) {
            load_stage(Ah4, Al4, Bh4, sb, (c + 3) & 3, c + 3, m0, n0, tid);
            CP_COMMIT();
        }
    }

    // epilogue
#pragma unroll
    for (int f = 0; f < 2; ++f) {
        const int grow = m0 + wm * 32 + f * 16 + (lane >> 2);
        float ss0 = 0.f, ss1 = 0.f;
#pragma unroll
        for (int j = 0; j < 4; ++j) {
            const int col = n0 + wn * 32 + j * 8 + (lane & 3) * 2;
            const float2 bb = *(const float2*)(bias + col);
            float2 o0 = make_float2(acc[f][j][0] + bb.x, acc[f][j][1] + bb.y);
            float2 o1 = make_float2(acc[f][j][2] + bb.x, acc[f][j][3] + bb.y);
            if (doNorm) {
                const size_t p0 = ((size_t)grow * DD + col) >> 1;
                const size_t p1 = ((size_t)(grow + 8) * DD + col) >> 1;
                __nv_bfloat16 h00 = __float2bfloat16(o0.x), h01 = __float2bfloat16(o0.y);
                __nv_bfloat16 h10 = __float2bfloat16(o1.x), h11 = __float2bfloat16(o1.y);
                __nv_bfloat16 l00 = __float2bfloat16(o0.x - __bfloat162float(h00));
                __nv_bfloat16 l01 = __float2bfloat16(o0.y - __bfloat162float(h01));
                __nv_bfloat16 l10 = __float2bfloat16(o1.x - __bfloat162float(h10));
                __nv_bfloat16 l11 = __float2bfloat16(o1.y - __bfloat162float(h11));
                ((__nv_bfloat162*)gh_buf)[p0] = __nv_bfloat162(h00, h01);
                ((__nv_bfloat162*)gl_buf)[p0] = __nv_bfloat162(l00, l01);
                ((__nv_bfloat162*)gh_buf)[p1] = __nv_bfloat162(h10, h11);
                ((__nv_bfloat162*)gl_buf)[p1] = __nv_bfloat162(l10, l11);
                ss0 = fmaf(o0.x, o0.x, fmaf(o0.y, o0.y, ss0));
                ss1 = fmaf(o1.x, o1.x, fmaf(o1.y, o1.y, ss1));
            } else {
                float* c0 = C + (size_t)grow * DD;
                *(float2*)(c0 + col) = o0;
                *(float2*)(c0 + 8 * DD + col) = o1;
            }
        }
        if (doNorm) {
            ss0 += __shfl_xor_sync(0xffffffffu, ss0, 1);
            ss0 += __shfl_xor_sync(0xffffffffu, ss0, 2);
            ss1 += __shfl_xor_sync(0xffffffffu, ss1, 1);
            ss1 += __shfl_xor_sync(0xffffffffu, ss1, 2);
            if ((lane & 3) == 0) {
                const int l0 = wm * 32 + f * 16 + (lane >> 2);
                atomicAdd(&ssrow[l0], ss0);
                atomicAdd(&ssrow[l0 + 8], ss1);
            }
        }
    }
    if (doNorm) {
        __syncthreads();
        if (tid < 128) {
            const int h = n0 >> 6;
            norm_buf[h * TT + m0 + tid] = sqrtf(ssrow[tid]);
        }
    }
}

__global__ void __launch_bounds__(256, 2)
k_gemm_gv(const float* __restrict__ bg, const float* __restrict__ bv)
{
    if (blockIdx.z == 0)
        gemm_core((const uint4*)xh_buf, (const uint4*)xl_buf,
                  (const uint4*)wgh_buf, bg, nullptr, true);
    else
        gemm_core((const uint4*)xh_buf, (const uint4*)xl_buf,
                  (const uint4*)wvh_buf, bv, v_buf, false);
}

__global__ void __launch_bounds__(256, 2)
k_gemm_o(const float* __restrict__ bo, float* __restrict__ out)
{
    gemm_core((const uint4*)oh_buf, (const uint4*)ol_buf,
              (const uint4*)woh_buf, bo, out, false);
}

// ---------------- MMA banded scores (bf16 3-product) -------------------------
#define WTSZ   (SPAN * 128)
#define SMEM_S (2 * WTSZ)

__global__ void __launch_bounds__(256)
k_scores_mma()
{
    extern __shared__ char smem[];
    __shared__ float nwin[SPAN];
    __shared__ float rowsum[SIT];
    __shared__ float sinv[SIT];

    const uint32_t sbH = s2u(smem);
    const uint32_t sbL = sbH + WTSZ;
    const int tid  = threadIdx.x;
    const int wid  = tid >> 5;
    const int lane = tid & 31;
    const int i0 = blockIdx.x * SIT;
    const int h  = blockIdx.y;

    const int jstart0 = (i0 > WIN) ? (i0 - WIN) : 0;
    const int qbase   = i0 - jstart0;

    const uint4* gh4 = (const uint4*)gh_buf;
    const uint4* gl4 = (const uint4*)gl_buf;
#pragma unroll
    for (int t = 0; t < 6; ++t) {
        const int idx = t * 256 + tid;
        const int row = idx >> 3;
        const int q   = idx & 7;
        const uint32_t d = sw128((uint32_t)row * 128u + q * 16u);
        const size_t g = (size_t)(jstart0 + row) * (DD / 8) + h * 8 + q;
        CP_ASYNC16(sbH + d, gh4 + g);
        CP_ASYNC16(sbL + d, gl4 + g);
    }
    CP_COMMIT();
    if (tid < SPAN) nwin[tid] = norm_buf[h * TT + jstart0 + tid];
    if (tid < SIT) rowsum[tid] = 0.f;
    CP_WAIT0();
    __syncthreads();

    const int wm = wid >> 1;
    const int wn = wid & 1;

    const int r  = lane & 7;
    const int md = lane >> 3;
    const int arow  = qbase + wm * 16 + (md & 1) * 8 + r;
    const uint32_t abyte = (md >> 1) * 16;
    const int brow0 = wn * 96 + (md >> 1) * 8 + r;
    const uint32_t bbyte = (md & 1) * 16;

    float acc[12][4];
#pragma unroll
    for (int nt = 0; nt < 12; ++nt)
#pragma unroll
        for (int e = 0; e < 4; ++e) acc[nt][e] = 0.f;

#pragma unroll
    for (int ks = 0; ks < 4; ++ks) {
        const uint32_t kb = ks * 32;
        uint32_t ah[4], al[4];
        const uint32_t aoff = sw128((uint32_t)arow * 128u + kb + abyte);
        ldsm_x4(ah[0], ah[1], ah[2], ah[3], sbH + aoff);
        ldsm_x4(al[0], al[1], al[2], al[3], sbL + aoff);
#pragma unroll
        for (int bt = 0; bt < 6; ++bt) {
            uint32_t bh[2][2], bl[2][2];
            const uint32_t boff = sw128((uint32_t)(brow0 + bt * 16) * 128u + kb + bbyte);
            ldsm_x4(bh[0][0], bh[0][1], bh[1][0], bh[1][1], sbH + boff);
            ldsm_x4(bl[0][0], bl[0][1], bl[1][0], bl[1][1], sbL + boff);
#pragma unroll
            for (int p = 0; p < 2; ++p) {
                mma16816(acc[2*bt + p], ah, bh[p]);
                mma16816(acc[2*bt + p], ah, bl[p]);
                mma16816(acc[2*bt + p], al, bh[p]);
            }
        }
    }

    const int quad = lane >> 2;
    const int cp2  = (lane & 3) * 2;
    const int gi0 = i0 + wm * 16 + quad;
    const int gi1 = gi0 + 8;
    const float ni0 = nwin[qbase + wm * 16 + quad];
    const float ni1 = nwin[qbase + wm * 16 + quad + 8];
    const int off0 = (gi0 > WIN) ? (gi0 - WIN) : 0;
    const int off1 = (gi1 > WIN) ? (gi1 - WIN) : 0;
    __half* pr0 = p_buf + (size_t)(h * TT + gi0) * PSTR;
    __half* pr1 = p_buf + (size_t)(h * TT + gi1) * PSTR;
    float ps0 = 0.f, ps1 = 0.f;

#pragma unroll
    for (int nt = 0; nt < 12; ++nt) {
        const int jl = wn * 96 + nt * 8 + cp2;
        const int jg = jstart0 + jl;
        const float nj0 = nwin[jl];
        const float nj1 = nwin[jl + 1];
#pragma unroll
        for (int e = 0; e < 4; ++e) {
            const int  jj = jg + (e & 1);
            const float nj = (e & 1) ? nj1 : nj0;
            const int  gi  = (e >> 1) ? gi1 : gi0;
            const float ni = (e >> 1) ? ni1 : ni0;
            const int  off = (e >> 1) ? off1 : off0;
            if (jj <= gi && jj >= off) {
                float c = acc[nt][e] / (ni * nj + 1e-8f);
                if (c != c) c = 0.f;
                float p = (c + 1.f) * 0.5f;
                ((e >> 1) ? pr1 : pr0)[jj - off] = __float2half_rn(p);
                if (e >> 1) ps1 += p; else ps0 += p;
            }
        }
    }

    ps0 += __shfl_xor_sync(0xffffffffu, ps0, 1);
    ps0 += __shfl_xor_sync(0xffffffffu, ps0, 2);
    ps1 += __shfl_xor_sync(0xffffffffu, ps1, 1);
    ps1 += __shfl_xor_sync(0xffffffffu, ps1, 2);
    if ((lane & 3) == 0) {
        atomicAdd(&rowsum[wm * 16 + quad], ps0);
        atomicAdd(&rowsum[wm * 16 + quad + 8], ps1);
    }
    __syncthreads();

    if (tid < SIT) {
        const int i   = i0 + tid;
        const int cnt = i - ((i > WIN) ? (i - WIN) : 0) + 1;
        float gm = (rowsum[tid] + 0.5f * (float)(TT - cnt)) * (1.f / (float)TT);
        float dn = gm + 0.5f;
        denom_buf[h * TT + i] = dn;
        sinv[tid] = 1.f / dn;
    }
    __syncthreads();
    if (tid < 32) {
        float s = sinv[tid] + sinv[tid + 32];
#pragma unroll
        for (int o = 16; o > 0; o >>= 1) s += __shfl_xor_sync(0xffffffffu, s, o);
        if (tid == 0) atomicAdd(&suminv_buf[h], s);
    }
}

// ---------------- softmax + attn@v: v-load overlapped with phase A ----------
#define SATT_STRIDE 20
#define ATTN_SMEM   (JTA * HDIM * 4 + JTA * SATT_STRIDE * 4 + 64)

__global__ void __launch_bounds__(256)
k_attnv()
{
    extern __shared__ char dynsm[];
    float (*vw)[HDIM]       = (float(*)[HDIM])dynsm;                 // [JTA][64]
    float (*sattn)[SATT_STRIDE] =
        (float(*)[SATT_STRIDE])(dynsm + JTA * HDIM * 4);             // [JTA][20]
    float* invs = (float*)(dynsm + JTA * HDIM * 4 + JTA * SATT_STRIDE * 4); // [16]

    const int i0  = blockIdx.x * IT;
    const int h   = blockIdx.y;
    const int tid = threadIdx.x;
    const int wid = tid >> 5;
    const int lane = tid & 31;

    const int jstart0 = (i0 > WIN) ? (i0 - WIN) : 0;
    const int span    = (i0 + IT - 1) - jstart0 + 1;

    // async v-window load — overlapped with phase A (which doesn't touch vw)
    {
        const uint32_t vw_base = s2u(dynsm);
        const float4* v4 = (const float4*)v_buf;
        for (int idx = tid; idx < span * 16; idx += 256) {
            const int jj = idx >> 4;
            const int q  = idx & 15;
            CP_ASYNC16(vw_base + (uint32_t)idx * 16u,
                       v4 + (size_t)(jstart0 + jj) * (DD / 4) + h * (HDIM / 4) + q);
        }
        CP_COMMIT();
    }

    // phase A: warp wid handles rows wid and wid+8
#pragma unroll
    for (int rr = 0; rr < 2; ++rr) {
        const int w = wid + rr * 8;
        const int i = i0 + w;
        const size_t row = (size_t)h * TT + i;
        const float fit  = 1.f / (denom_buf[row] * suminv_buf[h]);
        const int off = ((i > WIN) ? (i - WIN) : 0) - jstart0;
        const int wi  = i - jstart0;

        float m = -1e30f;
        for (int q = lane; q < JTA; q += 32) {
            bool in = (q >= off) && (q <= wi);
            float s = in ? fit * __half2float(p_buf[row * PSTR + (q - off)]) : -1e30f;
            sattn[q][w] = s;
            m = fmaxf(m, s);
        }
#pragma unroll
        for (int o = 16; o > 0; o >>= 1) m = fmaxf(m, __shfl_xor_sync(0xffffffffu, m, o));

        float ss = 0.f;
        for (int q = lane; q < JTA; q += 32) {
            float e = __expf(sattn[q][w] - m);
            sattn[q][w] = e;
            ss += e;
        }
#pragma unroll
        for (int o = 16; o > 0; o >>= 1) ss += __shfl_xor_sync(0xffffffffu, ss, o);
        if (lane == 0) invs[w] = 1.f / ss;
    }
    CP_WAIT0();
    __syncthreads();

    // phase B: thread = (d, row-group of 4); unroll x2 with dual accumulators
    {
        const int d   = tid & 63;
        const int grp = tid >> 6;
        float a0 = 0.f, a1 = 0.f, a2 = 0.f, a3 = 0.f;
        float b0 = 0.f, b1 = 0.f, b2 = 0.f, b3 = 0.f;
        int jj = 0;
        for (; jj + 1 < span; jj += 2) {
            const float v0 = vw[jj][d];
            const float v1 = vw[jj + 1][d];
            const float4 s0 = *(const float4*)&sattn[jj][grp * 4];
            const float4 s1 = *(const float4*)&sattn[jj + 1][grp * 4];
            a0 = fmaf(s0.x, v0, a0);  a1 = fmaf(s0.y, v0, a1);
            a2 = fmaf(s0.z, v0, a2);  a3 = fmaf(s0.w, v0, a3);
            b0 = fmaf(s1.x, v1, b0);  b1 = fmaf(s1.y, v1, b1);
            b2 = fmaf(s1.z, v1, b2);  b3 = fmaf(s1.w, v1, b3);
        }
        if (jj < span) {
            const float v0 = vw[jj][d];
            const float4 s0 = *(const float4*)&sattn[jj][grp * 4];
            a0 = fmaf(s0.x, v0, a0);  a1 = fmaf(s0.y, v0, a1);
            a2 = fmaf(s0.z, v0, a2);  a3 = fmaf(s0.w, v0, a3);
        }
        a0 += b0; a1 += b1; a2 += b2; a3 += b3;

        const float r0 = a0 * invs[grp * 4 + 0];
        const float r1 = a1 * invs[grp * 4 + 1];
        const float r2 = a2 * invs[grp * 4 + 2];
        const float r3 = a3 * invs[grp * 4 + 3];
        const size_t base = (size_t)(i0 + grp * 4) * DD + h * HDIM + d;
#pragma unroll
        for (int rI = 0; rI < 4; ++rI) {
            const float val = (rI == 0) ? r0 : (rI == 1) ? r1 : (rI == 2) ? r2 : r3;
            const size_t idx = base + (size_t)rI * DD;
            __half hv = __float2half_rn(val);
            __half lv = __float2half_rn(val - __half2float(hv));
            oh_buf[idx] = hv;
            ol_buf[idx] = lv;
        }
    }
}

// ---------------- launch ---------------------------------------------------
extern "C" void kernel_launch(void* const* d_in, const int* in_sizes, int n_in,
                              void* d_out, int out_size)
{
    const float* x  = (const float*)d_in[0];
    const float* Wg = (const float*)d_in[1];
    const float* bg = (const float*)d_in[2];
    const float* Wv = (const float*)d_in[3];
    const float* bv = (const float*)d_in[4];
    const float* Wo = (const float*)d_in[5];
    const float* bo = (const float*)d_in[6];
    float* out = (float*)d_out;

    cudaFuncSetAttribute(k_gemm_gv,   cudaFuncAttributeMaxDynamicSharedMemorySize, SMEM_G);
    cudaFuncSetAttribute(k_gemm_o,    cudaFuncAttributeMaxDynamicSharedMemorySize, SMEM_G);
    cudaFuncSetAttribute(k_scores_mma,cudaFuncAttributeMaxDynamicSharedMemorySize, SMEM_S);
    cudaFuncSetAttribute(k_attnv,     cudaFuncAttributeMaxDynamicSharedMemorySize, ATTN_SMEM);

    k_conv_all<<<2560, 256>>>(x, Wg, Wv, Wo);                 // #1

    dim3 gemm_gv(DD / 64, TT / 128, 2);
    k_gemm_gv<<<gemm_gv, 256, SMEM_G>>>(bg, bv);              // #2

    dim3 sc_grid(TT / SIT, NH);
    k_scores_mma<<<sc_grid, 256, SMEM_S>>>();                 // #3

    dim3 av_grid(TT / IT, NH);
    k_attnv<<<av_grid, 256, ATTN_SMEM>>>();                   // #4 (ncu slot)

    dim3 gemm_o(DD / 64, TT / 128, 1);
    k_gemm_o<<<gemm_o, 256, SMEM_G>>>(bo, out);               // #5
}

// round 15
// speedup vs baseline: 1.3987x; 1.1004x over previous
#include <cuda_runtime.h>
#include <cuda_bf16.h>
#include <cuda_fp16.h>
#include <math.h>
#include <stdint.h>

#define TT   2048
#define DD   1024
#define NH   16
#define HDIM 64
#define WIN  128
#define PSTR 132
#define IT   16
#define JTA  148
#define SIT  64     // scores i-tile
#define SPAN 192    // scores j-window (64 + 128)

// ---------------- scratch (static device globals; no allocation) ----------
__device__ float v_buf[TT * DD];
__device__ float norm_buf[NH * TT];
__device__ float denom_buf[NH * TT];
__device__ float suminv_buf[NH];
__device__ __half p_buf[(size_t)NH * TT * PSTR];   // fp16 score matrix

__device__ __half xh_buf[TT * DD], xl_buf[TT * DD];
__device__ __half oh_buf[TT * DD], ol_buf[TT * DD];
__device__ __half wgh_buf[DD * DD], wvh_buf[DD * DD], woh_buf[DD * DD];
__device__ __nv_bfloat16 gh_buf[TT * DD], gl_buf[TT * DD];

// ---------------- PTX helpers ----------------------------------------------
__device__ __forceinline__ uint32_t s2u(const void* p) {
    uint32_t a;
    asm("{ .reg .u64 t; cvta.to.shared.u64 t, %1; cvt.u32.u64 %0, t; }"
        : "=r"(a) : "l"(p));
    return a;
}
#define CP_ASYNC16(dst, src) \
    asm volatile("cp.async.cg.shared.global [%0], [%1], 16;" :: "r"(dst), "l"(src))
#define CP_COMMIT()  asm volatile("cp.async.commit_group;" ::: "memory")
#define CP_WAIT2()   asm volatile("cp.async.wait_group 2;" ::: "memory")
#define CP_WAIT1()   asm volatile("cp.async.wait_group 1;" ::: "memory")
#define CP_WAIT0()   asm volatile("cp.async.wait_group 0;" ::: "memory")

__device__ __forceinline__ void ldsm_x4(uint32_t& r0, uint32_t& r1,
                                        uint32_t& r2, uint32_t& r3, uint32_t a) {
    asm volatile("ldmatrix.sync.aligned.m8n8.x4.shared.b16 {%0,%1,%2,%3}, [%4];"
                 : "=r"(r0), "=r"(r1), "=r"(r2), "=r"(r3) : "r"(a));
}
__device__ __forceinline__ void mma16816(float* d, const uint32_t* a, const uint32_t* b) {
    asm volatile(
        "mma.sync.aligned.m16n8k16.row.col.f32.bf16.bf16.f32 "
        "{%0,%1,%2,%3}, {%4,%5,%6,%7}, {%8,%9}, {%0,%1,%2,%3};"
        : "+f"(d[0]), "+f"(d[1]), "+f"(d[2]), "+f"(d[3])
        : "r"(a[0]), "r"(a[1]), "r"(a[2]), "r"(a[3]), "r"(b[0]), "r"(b[1]));
}
__device__ __forceinline__ void mma16816h(float* d, const uint32_t* a, const uint32_t* b) {
    asm volatile(
        "mma.sync.aligned.m16n8k16.row.col.f32.f16.f16.f32 "
        "{%0,%1,%2,%3}, {%4,%5,%6,%7}, {%8,%9}, {%0,%1,%2,%3};"
        : "+f"(d[0]), "+f"(d[1]), "+f"(d[2]), "+f"(d[3])
        : "r"(a[0]), "r"(a[1]), "r"(a[2]), "r"(a[3]), "r"(b[0]), "r"(b[1]));
}
__device__ __forceinline__ uint32_t sw64(uint32_t off) {
    return off ^ ((off >> 3) & 0x30u);
}
__device__ __forceinline__ uint32_t sw128(uint32_t off) {
    return off ^ ((off >> 3) & 0x70u);
}

// ---------------- conversions ------------------------------------------------
__device__ __forceinline__ void split_store_h(const float* __restrict__ src,
                                              __half* __restrict__ dh,
                                              __half* __restrict__ dl, int i)
{
    float4 v = ((const float4*)src)[i];
    __half h0 = __float2half_rn(v.x), h1 = __float2half_rn(v.y),
           h2 = __float2half_rn(v.z), h3 = __float2half_rn(v.w);
    __half l0 = __float2half_rn(v.x - __half2float(h0)),
           l1 = __float2half_rn(v.y - __half2float(h1)),
           l2 = __float2half_rn(v.z - __half2float(h2)),
           l3 = __float2half_rn(v.w - __half2float(h3));
    __half2 hp0(h0, h1), hp1(h2, h3), lp0(l0, l1), lp1(l2, l3);
    uint2 uh, ul;
    uh.x = *(unsigned*)&hp0; uh.y = *(unsigned*)&hp1;
    ul.x = *(unsigned*)&lp0; ul.y = *(unsigned*)&lp1;
    ((uint2*)dh)[i] = uh;
    ((uint2*)dl)[i] = ul;
}
__device__ __forceinline__ void single_store_h(const float* __restrict__ src,
                                               __half* __restrict__ dh, int i)
{
    float4 v = ((const float4*)src)[i];
    __half2 hp0(__float2half_rn(v.x), __float2half_rn(v.y));
    __half2 hp1(__float2half_rn(v.z), __float2half_rn(v.w));
    uint2 uh;
    uh.x = *(unsigned*)&hp0; uh.y = *(unsigned*)&hp1;
    ((uint2*)dh)[i] = uh;
}

__global__ void __launch_bounds__(256)
k_conv_all(const float* __restrict__ x,  const float* __restrict__ Wg,
           const float* __restrict__ Wv, const float* __restrict__ Wo)
{
    const int b = blockIdx.x;
    if (b == 0 && threadIdx.x < NH) suminv_buf[threadIdx.x] = 0.f;
    if (b < 1024) {
        const int i = b * 512 + threadIdx.x;
        split_store_h(x, xh_buf, xl_buf, i);
        split_store_h(x, xh_buf, xl_buf, i + 256);
    } else if (b < 1536) {
        const int i = (b - 1024) * 512 + threadIdx.x;
        single_store_h(Wg, wgh_buf, i);
        single_store_h(Wg, wgh_buf, i + 256);
    } else if (b < 2048) {
        const int i = (b - 1536) * 512 + threadIdx.x;
        single_store_h(Wv, wvh_buf, i);
        single_store_h(Wv, wvh_buf, i + 256);
    } else {
        const int i = (b - 2048) * 512 + threadIdx.x;
        single_store_h(Wo, woh_buf, i);
        single_store_h(Wo, woh_buf, i + 256);
    }
}

// ------- fp16 2-product GEMM, CTA tile 128x128 (single-wave grids) ----------
#define KC32   32
#define NC     (DD / KC32)
#define ATSZ   8192                 // 128 rows x 64B
#define STG    (3 * ATSZ)           // Ah, Al, Bh = 24576
#define NSTAGE 4
#define SMEM_G (NSTAGE * STG)       // 98304

__device__ __forceinline__ void load_stage(
    const uint4* __restrict__ Ah4, const uint4* __restrict__ Al4,
    const uint4* __restrict__ Bh4,
    uint32_t sb, int slot, int c, int m0, int n0, int tid)
{
    const uint32_t base = sb + slot * STG;
    const int q   = tid & 3;
    const int row = tid >> 2;           // 0..63
#pragma unroll
    for (int t = 0; t < 2; ++t) {
        const int rr = row + t * 64;    // 0..127
        const uint32_t so = sw64((uint32_t)rr * 64u + q * 16u);
        const size_t goA = (size_t)(m0 + rr) * (DD / 8) + c * 4 + q;
        const size_t goB = (size_t)(n0 + rr) * (DD / 8) + c * 4 + q;
        CP_ASYNC16(base + so,            Ah4 + goA);
        CP_ASYNC16(base + ATSZ + so,     Al4 + goA);
        CP_ASYNC16(base + 2 * ATSZ + so, Bh4 + goB);
    }
}

__device__ __forceinline__ void gemm_core(
    const uint4* __restrict__ Ah4, const uint4* __restrict__ Al4,
    const uint4* __restrict__ Bh4,
    const float* __restrict__ bias, float* __restrict__ C, bool doNorm)
{
    extern __shared__ char smem[];
    __shared__ float ssrow[2][128];
    const uint32_t sb = s2u(smem);
    const int tid  = threadIdx.x;
    const int wid  = tid >> 5;
    const int lane = tid & 31;
    const int n0 = blockIdx.x * 128, m0 = blockIdx.y * 128;

    const int wm = wid >> 1;            // 0..3 (m 32-row tile)
    const int wn = wid & 1;             // 0..1 (n 64-col tile = one head)

    const int r  = lane & 7;
    const int md = lane >> 3;
    const int rowA = wm * 32 + (md & 1) * 8 + r;
    const uint32_t bA = (md >> 1) * 16;
    const int rowB = wn * 64 + (md >> 1) * 8 + r;
    const uint32_t bB = (md & 1) * 16;

    if (doNorm) ((float*)ssrow)[tid] = 0.f;

    float acc[2][8][4];
#pragma unroll
    for (int f = 0; f < 2; ++f)
#pragma unroll
        for (int j = 0; j < 8; ++j)
#pragma unroll
            for (int e = 0; e < 4; ++e) acc[f][j][e] = 0.f;

    load_stage(Ah4, Al4, Bh4, sb, 0, 0, m0, n0, tid); CP_COMMIT();
    load_stage(Ah4, Al4, Bh4, sb, 1, 1, m0, n0, tid); CP_COMMIT();
    load_stage(Ah4, Al4, Bh4, sb, 2, 2, m0, n0, tid); CP_COMMIT();

#pragma unroll 1
    for (int c = 0; c < NC; ++c) {
        const int rem = NC - 1 - c;
        if (rem >= 2) CP_WAIT2(); else if (rem == 1) CP_WAIT1(); else CP_WAIT0();
        __syncthreads();

        const uint32_t base = sb + (c & 3) * STG;
        const uint32_t stAh = base;
        const uint32_t stAl = base + ATSZ;
        const uint32_t stBh = base + 2 * ATSZ;

#pragma unroll
        for (int ks = 0; ks < 2; ++ks) {
            const uint32_t kb = ks * 32;
            uint32_t ah[2][4], al[2][4];
#pragma unroll
            for (int f = 0; f < 2; ++f) {
                const uint32_t off = sw64((uint32_t)(rowA + f * 16) * 64u + kb + bA);
                ldsm_x4(ah[f][0], ah[f][1], ah[f][2], ah[f][3], stAh + off);
                ldsm_x4(al[f][0], al[f][1], al[f][2], al[f][3], stAl + off);
            }
            uint32_t bh[8][2];
#pragma unroll
            for (int p = 0; p < 4; ++p) {
                const uint32_t off = sw64((uint32_t)(rowB + p * 16) * 64u + kb + bB);
                ldsm_x4(bh[2*p][0], bh[2*p][1], bh[2*p+1][0], bh[2*p+1][1], stBh + off);
            }
#pragma unroll
            for (int f = 0; f < 2; ++f)
#pragma unroll
                for (int j = 0; j < 8; ++j) {
                    mma16816h(acc[f][j], ah[f], bh[j]);
                    mma16816h(acc[f][j], al[f], bh[j]);
                }
        }
        if (c + 3 < NC) {
            load_stage(Ah4, Al4, Bh4, sb, (c + 3) & 3, c + 3, m0, n0, tid);
            CP_COMMIT();
        }
    }

    // epilogue
#pragma unroll
    for (int f = 0; f < 2; ++f) {
        const int grow = m0 + wm * 32 + f * 16 + (lane >> 2);
        float ss0 = 0.f, ss1 = 0.f;
#pragma unroll
        for (int j = 0; j < 8; ++j) {
            const int col = n0 + wn * 64 + j * 8 + (lane & 3) * 2;
            const float2 bb = *(const float2*)(bias + col);
            float2 o0 = make_float2(acc[f][j][0] + bb.x, acc[f][j][1] + bb.y);
            float2 o1 = make_float2(acc[f][j][2] + bb.x, acc[f][j][3] + bb.y);
            if (doNorm) {
                const size_t p0 = ((size_t)grow * DD + col) >> 1;
                const size_t p1 = ((size_t)(grow + 8) * DD + col) >> 1;
                __nv_bfloat16 h00 = __float2bfloat16(o0.x), h01 = __float2bfloat16(o0.y);
                __nv_bfloat16 h10 = __float2bfloat16(o1.x), h11 = __float2bfloat16(o1.y);
                __nv_bfloat16 l00 = __float2bfloat16(o0.x - __bfloat162float(h00));
                __nv_bfloat16 l01 = __float2bfloat16(o0.y - __bfloat162float(h01));
                __nv_bfloat16 l10 = __float2bfloat16(o1.x - __bfloat162float(h10));
                __nv_bfloat16 l11 = __float2bfloat16(o1.y - __bfloat162float(h11));
                ((__nv_bfloat162*)gh_buf)[p0] = __nv_bfloat162(h00, h01);
                ((__nv_bfloat162*)gl_buf)[p0] = __nv_bfloat162(l00, l01);
                ((__nv_bfloat162*)gh_buf)[p1] = __nv_bfloat162(h10, h11);
                ((__nv_bfloat162*)gl_buf)[p1] = __nv_bfloat162(l10, l11);
                ss0 = fmaf(o0.x, o0.x, fmaf(o0.y, o0.y, ss0));
                ss1 = fmaf(o1.x, o1.x, fmaf(o1.y, o1.y, ss1));
            } else {
                float* c0 = C + (size_t)grow * DD;
                *(float2*)(c0 + col) = o0;
                *(float2*)(c0 + 8 * DD + col) = o1;
            }
        }
        if (doNorm) {
            ss0 += __shfl_xor_sync(0xffffffffu, ss0, 1);
            ss0 += __shfl_xor_sync(0xffffffffu, ss0, 2);
            ss1 += __shfl_xor_sync(0xffffffffu, ss1, 1);
            ss1 += __shfl_xor_sync(0xffffffffu, ss1, 2);
            if ((lane & 3) == 0) {
                const int l0 = wm * 32 + f * 16 + (lane >> 2);
                atomicAdd(&ssrow[wn][l0], ss0);
                atomicAdd(&ssrow[wn][l0 + 8], ss1);
            }
        }
    }
    if (doNorm) {
        __syncthreads();
        // 2 heads per block: head = n0/64 + (tid>>7), row = tid&127
        const int h = (n0 >> 6) + (tid >> 7);
        norm_buf[h * TT + m0 + (tid & 127)] = sqrtf(ssrow[tid >> 7][tid & 127]);
    }
}

__global__ void __launch_bounds__(256, 2)
k_gemm_gv(const float* __restrict__ bg, const float* __restrict__ bv)
{
    if (blockIdx.z == 0)
        gemm_core((const uint4*)xh_buf, (const uint4*)xl_buf,
                  (const uint4*)wgh_buf, bg, nullptr, true);
    else
        gemm_core((const uint4*)xh_buf, (const uint4*)xl_buf,
                  (const uint4*)wvh_buf, bv, v_buf, false);
}

__global__ void __launch_bounds__(256, 2)
k_gemm_o(const float* __restrict__ bo, float* __restrict__ out)
{
    gemm_core((const uint4*)oh_buf, (const uint4*)ol_buf,
              (const uint4*)woh_buf, bo, out, false);
}

// ---------------- MMA banded scores (bf16 3-product) -------------------------
#define WTSZ   (SPAN * 128)
#define SMEM_S (2 * WTSZ)

__global__ void __launch_bounds__(256)
k_scores_mma()
{
    extern __shared__ char smem[];
    __shared__ float nwin[SPAN];
    __shared__ float rowsum[SIT];
    __shared__ float sinv[SIT];

    const uint32_t sbH = s2u(smem);
    const uint32_t sbL = sbH + WTSZ;
    const int tid  = threadIdx.x;
    const int wid  = tid >> 5;
    const int lane = tid & 31;
    const int i0 = blockIdx.x * SIT;
    const int h  = blockIdx.y;

    const int jstart0 = (i0 > WIN) ? (i0 - WIN) : 0;
    const int qbase   = i0 - jstart0;

    const uint4* gh4 = (const uint4*)gh_buf;
    const uint4* gl4 = (const uint4*)gl_buf;
#pragma unroll
    for (int t = 0; t < 6; ++t) {
        const int idx = t * 256 + tid;
        const int row = idx >> 3;
        const int q   = idx & 7;
        const uint32_t d = sw128((uint32_t)row * 128u + q * 16u);
        const size_t g = (size_t)(jstart0 + row) * (DD / 8) + h * 8 + q;
        CP_ASYNC16(sbH + d, gh4 + g);
        CP_ASYNC16(sbL + d, gl4 + g);
    }
    CP_COMMIT();
    if (tid < SPAN) nwin[tid] = norm_buf[h * TT + jstart0 + tid];
    if (tid < SIT) rowsum[tid] = 0.f;
    CP_WAIT0();
    __syncthreads();

    const int wm = wid >> 1;
    const int wn = wid & 1;

    const int r  = lane & 7;
    const int md = lane >> 3;
    const int arow  = qbase + wm * 16 + (md & 1) * 8 + r;
    const uint32_t abyte = (md >> 1) * 16;
    const int brow0 = wn * 96 + (md >> 1) * 8 + r;
    const uint32_t bbyte = (md & 1) * 16;

    float acc[12][4];
#pragma unroll
    for (int nt = 0; nt < 12; ++nt)
#pragma unroll
        for (int e = 0; e < 4; ++e) acc[nt][e] = 0.f;

#pragma unroll
    for (int ks = 0; ks < 4; ++ks) {
        const uint32_t kb = ks * 32;
        uint32_t ah[4], al[4];
        const uint32_t aoff = sw128((uint32_t)arow * 128u + kb + abyte);
        ldsm_x4(ah[0], ah[1], ah[2], ah[3], sbH + aoff);
        ldsm_x4(al[0], al[1], al[2], al[3], sbL + aoff);
#pragma unroll
        for (int bt = 0; bt < 6; ++bt) {
            uint32_t bh[2][2], bl[2][2];
            const uint32_t boff = sw128((uint32_t)(brow0 + bt * 16) * 128u + kb + bbyte);
            ldsm_x4(bh[0][0], bh[0][1], bh[1][0], bh[1][1], sbH + boff);
            ldsm_x4(bl[0][0], bl[0][1], bl[1][0], bl[1][1], sbL + boff);
#pragma unroll
            for (int p = 0; p < 2; ++p) {
                mma16816(acc[2*bt + p], ah, bh[p]);
                mma16816(acc[2*bt + p], ah, bl[p]);
                mma16816(acc[2*bt + p], al, bh[p]);
            }
        }
    }

    const int quad = lane >> 2;
    const int cp2  = (lane & 3) * 2;
    const int gi0 = i0 + wm * 16 + quad;
    const int gi1 = gi0 + 8;
    const float ni0 = nwin[qbase + wm * 16 + quad];
    const float ni1 = nwin[qbase + wm * 16 + quad + 8];
    const int off0 = (gi0 > WIN) ? (gi0 - WIN) : 0;
    const int off1 = (gi1 > WIN) ? (gi1 - WIN) : 0;
    __half* pr0 = p_buf + (size_t)(h * TT + gi0) * PSTR;
    __half* pr1 = p_buf + (size_t)(h * TT + gi1) * PSTR;
    float ps0 = 0.f, ps1 = 0.f;

#pragma unroll
    for (int nt = 0; nt < 12; ++nt) {
        const int jl = wn * 96 + nt * 8 + cp2;
        const int jg = jstart0 + jl;
        const float nj0 = nwin[jl];
        const float nj1 = nwin[jl + 1];
#pragma unroll
        for (int e = 0; e < 4; ++e) {
            const int  jj = jg + (e & 1);
            const float nj = (e & 1) ? nj1 : nj0;
            const int  gi  = (e >> 1) ? gi1 : gi0;
            const float ni = (e >> 1) ? ni1 : ni0;
            const int  off = (e >> 1) ? off1 : off0;
            if (jj <= gi && jj >= off) {
                float c = acc[nt][e] / (ni * nj + 1e-8f);
                if (c != c) c = 0.f;
                float p = (c + 1.f) * 0.5f;
                ((e >> 1) ? pr1 : pr0)[jj - off] = __float2half_rn(p);
                if (e >> 1) ps1 += p; else ps0 += p;
            }
        }
    }

    ps0 += __shfl_xor_sync(0xffffffffu, ps0, 1);
    ps0 += __shfl_xor_sync(0xffffffffu, ps0, 2);
    ps1 += __shfl_xor_sync(0xffffffffu, ps1, 1);
    ps1 += __shfl_xor_sync(0xffffffffu, ps1, 2);
    if ((lane & 3) == 0) {
        atomicAdd(&rowsum[wm * 16 + quad], ps0);
        atomicAdd(&rowsum[wm * 16 + quad + 8], ps1);
    }
    __syncthreads();

    if (tid < SIT) {
        const int i   = i0 + tid;
        const int cnt = i - ((i > WIN) ? (i - WIN) : 0) + 1;
        float gm = (rowsum[tid] + 0.5f * (float)(TT - cnt)) * (1.f / (float)TT);
        float dn = gm + 0.5f;
        denom_buf[h * TT + i] = dn;
        sinv[tid] = 1.f / dn;
    }
    __syncthreads();
    if (tid < 32) {
        float s = sinv[tid] + sinv[tid + 32];
#pragma unroll
        for (int o = 16; o > 0; o >>= 1) s += __shfl_xor_sync(0xffffffffu, s, o);
        if (tid == 0) atomicAdd(&suminv_buf[h], s);
    }
}

// ---------------- softmax + attn@v (no max pass; v-load overlapped) ---------
#define SATT_STRIDE 20
#define ATTN_SMEM   (JTA * HDIM * 4 + JTA * SATT_STRIDE * 4 + 64)

__global__ void __launch_bounds__(256)
k_attnv()
{
    extern __shared__ char dynsm[];
    float (*vw)[HDIM]       = (float(*)[HDIM])dynsm;
    float (*sattn)[SATT_STRIDE] =
        (float(*)[SATT_STRIDE])(dynsm + JTA * HDIM * 4);
    float* invs = (float*)(dynsm + JTA * HDIM * 4 + JTA * SATT_STRIDE * 4);

    const int i0  = blockIdx.x * IT;
    const int h   = blockIdx.y;
    const int tid = threadIdx.x;
    const int wid = tid >> 5;
    const int lane = tid & 31;

    const int jstart0 = (i0 > WIN) ? (i0 - WIN) : 0;
    const int span    = (i0 + IT - 1) - jstart0 + 1;

    // async v-window load — overlapped with phase A
    {
        const uint32_t vw_base = s2u(dynsm);
        const float4* v4 = (const float4*)v_buf;
        for (int idx = tid; idx < span * 16; idx += 256) {
            const int jj = idx >> 4;
            const int q  = idx & 15;
            CP_ASYNC16(vw_base + (uint32_t)idx * 16u,
                       v4 + (size_t)(jstart0 + jj) * (DD / 4) + h * (HDIM / 4) + q);
        }
        CP_COMMIT();
    }

    // phase A (single pass): logits = fit*p ∈ [0, ~1.5e-3] — no max needed
#pragma unroll
    for (int rr = 0; rr < 2; ++rr) {
        const int w = wid + rr * 8;
        const int i = i0 + w;
        const size_t row = (size_t)h * TT + i;
        const float fit  = 1.f / (denom_buf[row] * suminv_buf[h]);
        const int off = ((i > WIN) ? (i - WIN) : 0) - jstart0;
        const int wi  = i - jstart0;

        float ss = 0.f;
        for (int q = lane; q < JTA; q += 32) {
            const bool in = (q >= off) && (q <= wi);
            float e = in ? __expf(fit * __half2float(p_buf[row * PSTR + (q - off)])) : 0.f;
            sattn[q][w] = e;
            ss += e;
        }
#pragma unroll
        for (int o = 16; o > 0; o >>= 1) ss += __shfl_xor_sync(0xffffffffu, ss, o);
        if (lane == 0) invs[w] = 1.f / ss;
    }
    CP_WAIT0();
    __syncthreads();

    // phase B: thread = (d, row-group of 4); unroll x2 with dual accumulators
    {
        const int d   = tid & 63;
        const int grp = tid >> 6;
        float a0 = 0.f, a1 = 0.f, a2 = 0.f, a3 = 0.f;
        float b0 = 0.f, b1 = 0.f, b2 = 0.f, b3 = 0.f;
        int jj = 0;
        for (; jj + 1 < span; jj += 2) {
            const float v0 = vw[jj][d];
            const float v1 = vw[jj + 1][d];
            const float4 s0 = *(const float4*)&sattn[jj][grp * 4];
            const float4 s1 = *(const float4*)&sattn[jj + 1][grp * 4];
            a0 = fmaf(s0.x, v0, a0);  a1 = fmaf(s0.y, v0, a1);
            a2 = fmaf(s0.z, v0, a2);  a3 = fmaf(s0.w, v0, a3);
            b0 = fmaf(s1.x, v1, b0);  b1 = fmaf(s1.y, v1, b1);
            b2 = fmaf(s1.z, v1, b2);  b3 = fmaf(s1.w, v1, b3);
        }
        if (jj < span) {
            const float v0 = vw[jj][d];
            const float4 s0 = *(const float4*)&sattn[jj][grp * 4];
            a0 = fmaf(s0.x, v0, a0);  a1 = fmaf(s0.y, v0, a1);
            a2 = fmaf(s0.z, v0, a2);  a3 = fmaf(s0.w, v0, a3);
        }
        a0 += b0; a1 += b1; a2 += b2; a3 += b3;

        const float r0 = a0 * invs[grp * 4 + 0];
        const float r1 = a1 * invs[grp * 4 + 1];
        const float r2 = a2 * invs[grp * 4 + 2];
        const float r3 = a3 * invs[grp * 4 + 3];
        const size_t base = (size_t)(i0 + grp * 4) * DD + h * HDIM + d;
#pragma unroll
        for (int rI = 0; rI < 4; ++rI) {
            const float val = (rI == 0) ? r0 : (rI == 1) ? r1 : (rI == 2) ? r2 : r3;
            const size_t idx = base + (size_t)rI * DD;
            __half hv = __float2half_rn(val);
            __half lv = __float2half_rn(val - __half2float(hv));
            oh_buf[idx] = hv;
            ol_buf[idx] = lv;
        }
    }
}

// ---------------- launch ---------------------------------------------------
extern "C" void kernel_launch(void* const* d_in, const int* in_sizes, int n_in,
                              void* d_out, int out_size)
{
    const float* x  = (const float*)d_in[0];
    const float* Wg = (const float*)d_in[1];
    const float* bg = (const float*)d_in[2];
    const float* Wv = (const float*)d_in[3];
    const float* bv = (const float*)d_in[4];
    const float* Wo = (const float*)d_in[5];
    const float* bo = (const float*)d_in[6];
    float* out = (float*)d_out;

    cudaFuncSetAttribute(k_gemm_gv,   cudaFuncAttributeMaxDynamicSharedMemorySize, SMEM_G);
    cudaFuncSetAttribute(k_gemm_o,    cudaFuncAttributeMaxDynamicSharedMemorySize, SMEM_G);
    cudaFuncSetAttribute(k_scores_mma,cudaFuncAttributeMaxDynamicSharedMemorySize, SMEM_S);
    cudaFuncSetAttribute(k_attnv,     cudaFuncAttributeMaxDynamicSharedMemorySize, ATTN_SMEM);

    k_conv_all<<<2560, 256>>>(x, Wg, Wv, Wo);                 // #1

    dim3 gemm_gv(DD / 128, TT / 128, 2);                      // 256 CTAs = 1 wave
    k_gemm_gv<<<gemm_gv, 256, SMEM_G>>>(bg, bv);              // #2

    dim3 sc_grid(TT / SIT, NH);
    k_scores_mma<<<sc_grid, 256, SMEM_S>>>();                 // #3

    dim3 av_grid(TT / IT, NH);
    k_attnv<<<av_grid, 256, ATTN_SMEM>>>();                   // #4 (ncu slot)

    dim3 gemm_o(DD / 128, TT / 128, 1);                       // 128 CTAs = 1 wave
    k_gemm_o<<<gemm_o, 256, SMEM_G>>>(bo, out);               // #5
}